// round 14
// baseline (speedup 1.0000x reference)
#include <cuda_runtime.h>
#include <cuda_bf16.h>
#include <math.h>
#include <stdint.h>

// ---------------------------------------------------------------------------
// Static device scratch. Activations in (B, E, C) layout: x[(b*E+e)*C + c].
// ---------------------------------------------------------------------------
__device__ float  g_bufA[8388608];
__device__ float  g_bufB[8388608];
__device__ float  g_bufU[4194304];
__device__ float  g_bufY[8388608];
__device__ float  g_wt[400000];      // transposed fp32 weights (conv_small)
__device__ __align__(16) __nv_bfloat16 g_wb[774144];   // fragment-ordered, interleaved {hi0,hi1,lo0,lo1}
__device__ double g_stats[1024];
__device__ float2 g_mstat[512];

__device__ __forceinline__ uint32_t smem_u32(const void* p) {
    uint32_t a;
    asm("{ .reg .u64 t; cvta.to.shared.u64 t, %1; cvt.u32.u64 %0, t; }" : "=r"(a) : "l"(p));
    return a;
}

#define STS16(a, v) \
    asm volatile("st.shared.b16 [%0], %1;" :: "r"(a), "h"(v) : "memory")

#define STS128Z(a) \
    asm volatile("st.shared.v4.b32 [%0], {%1, %1, %1, %1};" :: "r"(a), "r"(0u) : "memory")

#define LDMX4(r, addr) \
    asm volatile("ldmatrix.sync.aligned.m8n8.x4.shared.b16 {%0,%1,%2,%3}, [%4];" \
        : "=r"((r)[0]), "=r"((r)[1]), "=r"((r)[2]), "=r"((r)[3]) : "r"(addr))

#define LDS128(r0, r1, r2, r3, addr) \
    asm volatile("ld.shared.v4.b32 {%0,%1,%2,%3}, [%4];" \
        : "=r"(r0), "=r"(r1), "=r"(r2), "=r"(r3) : "r"(addr))

#define CPASYNC16(saddr, gptr) \
    asm volatile("cp.async.cg.shared.global [%0], [%1], 16;" \
        :: "r"(saddr), "l"(gptr) : "memory")

#define CPCOMMIT() asm volatile("cp.async.commit_group;" ::: "memory")
#define CPWAIT0()  asm volatile("cp.async.wait_group 0;" ::: "memory")

#define MMA16816(d, a, b0, b1) \
    asm volatile("mma.sync.aligned.m16n8k16.row.col.f32.bf16.bf16.f32 " \
        "{%0,%1,%2,%3}, {%4,%5,%6,%7}, {%8,%9}, {%0,%1,%2,%3};" \
        : "+f"((d)[0]), "+f"((d)[1]), "+f"((d)[2]), "+f"((d)[3]) \
        : "r"((a)[0]), "r"((a)[1]), "r"((a)[2]), "r"((a)[3]), "r"(b0), "r"(b1))

__device__ __forceinline__ unsigned short bfbits(__nv_bfloat16 h) {
    return *reinterpret_cast<unsigned short*>(&h);
}

// ---------------------------------------------------------------------------
// fp32 weight transpose (conv_small path) + stats zeroing (fused)
// ---------------------------------------------------------------------------
__global__ void wtrans_all(const float* __restrict__ W0, const float* __restrict__ W1,
                           const float* __restrict__ W2, const float* __restrict__ W3,
                           const float* __restrict__ W4, const float* __restrict__ W5,
                           const float* __restrict__ W6, const float* __restrict__ W7,
                           float* __restrict__ wt, double* __restrict__ stats)
{
    int i = blockIdx.x * 256 + threadIdx.x;
    if (i < 1024) stats[i] = 0.0;
    if (i >= 324160) return;
    const int Ks[8]   = {1280, 640, 640, 320, 320, 160, 160, 40};
    const int Cs[8]   = {128, 128, 64, 64, 32, 32, 8, 8};
    const int offs[9] = {0, 163840, 245760, 286720, 307200, 317440, 322560, 323840, 324160};
    const float* Ws[8] = {W0, W1, W2, W3, W4, W5, W6, W7};
    int seg = 0;
    while (i >= offs[seg + 1]) seg++;
    int j = i - offs[seg];
    int K = Ks[seg], C = Cs[seg];
    int k = j / C, o = j % C;
    wt[i] = Ws[seg][(size_t)o * K + k];
}

// ---------------------------------------------------------------------------
// Fragment-ordered bf16 weights, 48-k chunks (40 real + 8 pad), hi/lo
// interleaved per uint4: {hi_reg0, hi_reg1, lo_reg0, lo_reg1}.
// ---------------------------------------------------------------------------
__global__ void wbf48(const float* __restrict__ W0, const float* __restrict__ W1,
                      const float* __restrict__ W2, const float* __restrict__ W3,
                      const float* __restrict__ W4, const float* __restrict__ W5,
                      __nv_bfloat16* __restrict__ wb)
{
    int i = blockIdx.x * 256 + threadIdx.x;
    if (i >= 774144) return;
    const int CINs[6]  = {256, 128, 128, 64, 64, 32};
    const int COUTs[6] = {128, 128, 64, 64, 32, 32};
    const int offs[7]  = {0, 393216, 589824, 688128, 737280, 761856, 774144};
    const float* Ws[6] = {W0, W1, W2, W3, W4, W5};
    int seg = 0;
    while (i >= offs[seg + 1]) seg++;
    int j = i - offs[seg];
    int CIN = CINs[seg], COUT = COUTs[seg];
    int half = j & 1;
    int reg  = (j >> 1) & 3;
    int lane = (j >> 3) & 31;
    int t    = j >> 8;
    int ka   = t % 3;  t /= 3;
    int naG  = t % (COUT / 8);
    int chunk = t / (COUT / 8);
    int rr = reg & 1;
    bool lo = (reg >= 2);
    int n  = naG * 8 + (lane >> 2);
    int kk = ka * 16 + (lane & 3) * 2 + half + rr * 8;
    float v = 0.f;
    if (kk < 40) {
        int s = kk >> 3, cc = kk & 7;
        int c = chunk * 8 + cc;
        v = Ws[seg][(size_t)n * (CIN * 5) + c * 5 + s];
    }
    __nv_bfloat16 h = __float2bfloat16(v);
    wb[i] = lo ? __float2bfloat16(v - __bfloat162float(h)) : h;
}

// ---------------------------------------------------------------------------
// fe (B, C, E) -> (B, E, C) tiled transpose
// ---------------------------------------------------------------------------
__global__ void xpose(const float* __restrict__ in, float* __restrict__ outT,
                      int E, int C) {
    __shared__ float tile[32][33];
    int bb = blockIdx.z;
    int e0 = blockIdx.x * 32, c0 = blockIdx.y * 32;
    int tx = threadIdx.x, ty = threadIdx.y;          // (32, 8)
    const float* inb = in + (size_t)bb * C * E;
    float* ob = outT + (size_t)bb * E * C;
#pragma unroll
    for (int j = 0; j < 32; j += 8)
        tile[ty + j][tx] = inb[(size_t)(c0 + ty + j) * E + e0 + tx];
    __syncthreads();
#pragma unroll
    for (int j = 0; j < 32; j += 8)
        ob[(size_t)(e0 + ty + j) * C + c0 + tx] = tile[tx][ty + j];
}

// ---------------------------------------------------------------------------
// Tensor-core mesh conv (m16n8k16 bf16 mma.sync), 48-k chunks (R12 pipeline).
// NORM: fused inorm+relu on the gathered input.
// STATS: epilogue accumulates per-column (sum, sumsq) of the output into
//        g_stats via smem float partials (replaces the inorm_partial pass).
// ---------------------------------------------------------------------------
template<int CIN, int COUT, bool NORM, bool STATS>
__global__ __launch_bounds__(256, 2) void conv_t(
    const float* __restrict__ x, const int4* __restrict__ gemm,
    const __nv_bfloat16* __restrict__ Wb, const float2* __restrict__ mstat,
    const float* __restrict__ bias, float* __restrict__ out,
    double* __restrict__ stats, int E)
{
    constexpr int CHUNKS = CIN / 8;
    constexpr int NA = COUT / 16;
    constexpr int PITCH = 112;
    constexpr int ABUF = 128 * PITCH;
    constexpr int BU4  = COUT * 12;
    constexpr int BBUF = BU4 * 16;

    extern __shared__ char smem_raw[];
    const uint32_t sAU = smem_u32(smem_raw);
    const uint32_t sBU = sAU + 4 * ABUF;
    int4* sIdx = reinterpret_cast<int4*>(smem_raw + 4 * ABUF + 2 * BBUF);

    __shared__ float sS[STATS ? COUT : 1];
    __shared__ float sQ[STATS ? COUT : 1];

    const int tid = threadIdx.x;
    const int wid = tid >> 5, lane = tid & 31;
    const int wm = wid & 3, wn = wid >> 2;
    const int bb = blockIdx.y;
    const int e0 = blockIdx.x * 128;
    const float* xb = x + (size_t)bb * E * CIN;

    for (int i = tid; i < 128; i += 256) sIdx[i] = gemm[e0 + i];
    for (int i = tid; i < 4 * 128; i += 256)
        STS128Z(sAU + (uint32_t)(i >> 7) * ABUF + (uint32_t)(i & 127) * PITCH + 80);
    if constexpr (STATS) {
        for (int i = tid; i < COUT; i += 256) { sS[i] = 0.f; sQ[i] = 0.f; }
    }

    const int cc = tid & 7;
    const int elb = tid >> 3;

    float acc[2][NA][4];
#pragma unroll
    for (int ma = 0; ma < 2; ma++)
#pragma unroll
        for (int na = 0; na < NA; na++)
#pragma unroll
            for (int u = 0; u < 4; u++) acc[ma][na][u] = 0.f;

    const uint4* wb4 = reinterpret_cast<const uint4*>(Wb);

    auto stageB = [&](int chunk) {
        const uint32_t dst = sBU + (uint32_t)(chunk & 1) * BBUF;
        const uint4* src = wb4 + (size_t)chunk * BU4;
#pragma unroll
        for (int i = tid; i < BU4; i += 256)
            CPASYNC16(dst + (uint32_t)i * 16, src + i);
        CPCOMMIT();
    };

    stageB(0);

    float g[4][5];
    auto gather = [&](int chunk) {
        const float* xc = xb + chunk * 8 + cc;
        float2 mr = make_float2(0.f, 1.f);
        if constexpr (NORM) mr = mstat[bb * CIN + chunk * 8 + cc];
#pragma unroll
        for (int q = 0; q < 4; q++) {
            int el = elb + 32 * q;
            int4 n = sIdx[el];
            float xe = xc[(size_t)(e0 + el) * CIN];
            float f1 = xc[(size_t)n.x * CIN];
            float f2 = xc[(size_t)n.y * CIN];
            float f3 = xc[(size_t)n.z * CIN];
            float f4 = xc[(size_t)n.w * CIN];
            if constexpr (NORM) {
                xe = fmaxf((xe - mr.x) * mr.y, 0.f);
                f1 = fmaxf((f1 - mr.x) * mr.y, 0.f);
                f2 = fmaxf((f2 - mr.x) * mr.y, 0.f);
                f3 = fmaxf((f3 - mr.x) * mr.y, 0.f);
                f4 = fmaxf((f4 - mr.x) * mr.y, 0.f);
            }
            g[q][0] = xe;
            g[q][1] = f1 + f3;  g[q][2] = f2 + f4;
            g[q][3] = fabsf(f1 - f3);  g[q][4] = fabsf(f2 - f4);
        }
    };

    __syncthreads();
    gather(0);

    for (int chunk = 0; chunk < CHUNKS; chunk++) {
        const uint32_t bufHi = sAU + (uint32_t)((chunk & 1) * 2) * ABUF;
        const uint32_t bufLo = bufHi + ABUF;
#pragma unroll
        for (int q = 0; q < 4; q++) {
            int el = elb + 32 * q;
            uint32_t base = (uint32_t)el * PITCH + (uint32_t)cc * 2;
#pragma unroll
            for (int s = 0; s < 5; s++) {
                __nv_bfloat16 h = __float2bfloat16(g[q][s]);
                STS16(bufHi + base + s * 16, bfbits(h));
                STS16(bufLo + base + s * 16,
                      bfbits(__float2bfloat16(g[q][s] - __bfloat162float(h))));
            }
        }
        CPWAIT0();
        __syncthreads();
        if (chunk + 1 < CHUNKS) stageB(chunk + 1);
        if (chunk + 1 < CHUNKS) gather(chunk + 1);
        const uint32_t bB = sBU + (uint32_t)(chunk & 1) * BBUF;
#pragma unroll
        for (int ka = 0; ka < 3; ka++) {
            uint32_t ah[2][4], al[2][4];
#pragma unroll
            for (int ma = 0; ma < 2; ma++) {
                uint32_t off = (uint32_t)(wm * 32 + ma * 16 + (lane & 15)) * PITCH
                             + (uint32_t)ka * 32 + ((lane >> 4) * 16);
                LDMX4(ah[ma], bufHi + off);
                LDMX4(al[ma], bufLo + off);
            }
#pragma unroll
            for (int na = 0; na < NA; na++) {
                uint32_t wx, wy, wz, ww;
                LDS128(wx, wy, wz, ww,
                       bB + (uint32_t)(((wn * NA + na) * 3 + ka) * 32 + lane) * 16);
#pragma unroll
                for (int ma = 0; ma < 2; ma++) {
                    MMA16816(acc[ma][na], ah[ma], wx, wy);
                    MMA16816(acc[ma][na], al[ma], wx, wy);
                    MMA16816(acc[ma][na], ah[ma], wz, ww);
                }
            }
        }
    }

    // ---- epilogue: acc + bias -> out (+ optional fused stats) ----
    const int rbase = e0 + wm * 32 + (lane >> 2);
#pragma unroll
    for (int ma = 0; ma < 2; ma++) {
#pragma unroll
        for (int na = 0; na < NA; na++) {
            int col = wn * NA * 8 + na * 8 + (lane & 3) * 2;
            float bx = bias[col], by = bias[col + 1];
            int row0 = rbase + ma * 16;
            float v0 = acc[ma][na][0] + bx, v1 = acc[ma][na][1] + by;
            float v2 = acc[ma][na][2] + bx, v3 = acc[ma][na][3] + by;
            float* p0 = out + ((size_t)bb * E + row0) * COUT + col;
            float* p1 = p0 + (size_t)8 * COUT;
            *reinterpret_cast<float2*>(p0) = make_float2(v0, v1);
            *reinterpret_cast<float2*>(p1) = make_float2(v2, v3);
            if constexpr (STATS) {
                atomicAdd(&sS[col],     v0 + v2);
                atomicAdd(&sS[col + 1], v1 + v3);
                atomicAdd(&sQ[col],     v0 * v0 + v2 * v2);
                atomicAdd(&sQ[col + 1], v1 * v1 + v3 * v3);
            }
        }
    }
    if constexpr (STATS) {
        __syncthreads();
        for (int i = tid; i < COUT; i += 256) {
            atomicAdd(&stats[((size_t)bb * COUT + i) * 2],     (double)sS[i]);
            atomicAdd(&stats[((size_t)bb * COUT + i) * 2 + 1], (double)sQ[i]);
        }
    }
}

// ---------------------------------------------------------------------------
// Small-Cout mesh-conv (COUT = 8), fp32, optional fused inorm+relu on input,
// optional fused output stats.
// ---------------------------------------------------------------------------
template<int CIN, bool NORM, bool STATS>
__global__ __launch_bounds__(256) void conv_small(
    const float* __restrict__ x, const int4* __restrict__ gemm,
    const float* __restrict__ Wt, const float2* __restrict__ mstat,
    const float* __restrict__ bias, float* __restrict__ out,
    double* __restrict__ stats, int E)
{
    constexpr int K = CIN * 5;
    __shared__ float sW[K * 8];
    __shared__ float2 sM[CIN];
    __shared__ float sS[STATS ? 8 : 1];
    __shared__ float sQ[STATS ? 8 : 1];
    int tid = threadIdx.x;
    int bb = blockIdx.y;
    for (int i = tid; i < K * 8; i += 256) sW[i] = Wt[i];
    if (NORM && tid < CIN) sM[tid] = mstat[bb * CIN + tid];
    if (STATS && tid < 8) { sS[tid] = 0.f; sQ[tid] = 0.f; }
    float acc[8];
#pragma unroll
    for (int o = 0; o < 8; o++) acc[o] = bias[o];
    __syncthreads();

    int e = blockIdx.x * 256 + tid;
    int4 n = gemm[e];
    const float* xb = x + (size_t)bb * E * CIN;
    const float4* r0 = reinterpret_cast<const float4*>(xb + (size_t)e * CIN);
    const float4* r1 = reinterpret_cast<const float4*>(xb + (size_t)n.x * CIN);
    const float4* r2 = reinterpret_cast<const float4*>(xb + (size_t)n.y * CIN);
    const float4* r3 = reinterpret_cast<const float4*>(xb + (size_t)n.z * CIN);
    const float4* r4 = reinterpret_cast<const float4*>(xb + (size_t)n.w * CIN);

#pragma unroll 2
    for (int c4 = 0; c4 < CIN / 4; c4++) {
        float4 xe = r0[c4], a1 = r1[c4], a2 = r2[c4], a3 = r3[c4], a4 = r4[c4];
#define PROC(COMP, CC)                                                         \
        {                                                                      \
            float xv = xe.COMP, v1 = a1.COMP, v2 = a2.COMP,                    \
                  v3 = a3.COMP, v4 = a4.COMP;                                  \
            if constexpr (NORM) {                                              \
                float2 mm = sM[c4 * 4 + CC];                                   \
                xv = fmaxf((xv - mm.x) * mm.y, 0.f);                           \
                v1 = fmaxf((v1 - mm.x) * mm.y, 0.f);                           \
                v2 = fmaxf((v2 - mm.x) * mm.y, 0.f);                           \
                v3 = fmaxf((v3 - mm.x) * mm.y, 0.f);                           \
                v4 = fmaxf((v4 - mm.x) * mm.y, 0.f);                           \
            }                                                                  \
            float g0 = xv;                                                     \
            float s1 = v1 + v3;                                                \
            float s2 = v2 + v4;                                                \
            float d1 = fabsf(v1 - v3);                                         \
            float d2 = fabsf(v2 - v4);                                         \
            const float* w = &sW[(c4 * 4 + CC) * 5 * 8];                       \
            for (int o = 0; o < 8; o++)                                        \
                acc[o] += g0 * w[o] + s1 * w[8 + o] + s2 * w[16 + o]           \
                        + d1 * w[24 + o] + d2 * w[32 + o];                     \
        }
        PROC(x, 0) PROC(y, 1) PROC(z, 2) PROC(w, 3)
#undef PROC
    }
    float* po = out + ((size_t)bb * E + e) * 8;
    *reinterpret_cast<float4*>(po)     = make_float4(acc[0], acc[1], acc[2], acc[3]);
    *reinterpret_cast<float4*>(po + 4) = make_float4(acc[4], acc[5], acc[6], acc[7]);
    if constexpr (STATS) {
#pragma unroll
        for (int o = 0; o < 8; o++) {
            atomicAdd(&sS[o], acc[o]);
            atomicAdd(&sQ[o], acc[o] * acc[o]);
        }
        __syncthreads();
        if (tid < 8) {
            atomicAdd(&stats[((size_t)bb * 8 + tid) * 2],     (double)sS[tid]);
            atomicAdd(&stats[((size_t)bb * 8 + tid) * 2 + 1], (double)sQ[tid]);
        }
    }
}

// ---------------------------------------------------------------------------
// unpool + skip
// ---------------------------------------------------------------------------
template<int C>
__global__ __launch_bounds__(256) void unpool_skip(
    const float* __restrict__ up, const int* __restrict__ unpool,
    const float* __restrict__ skip, float* __restrict__ out,
    int Eout, int Ein)
{
    constexpr int TE = 32;
    __shared__ float ssk[C][TE + 1];
    __shared__ int su[TE];
    int tid = threadIdx.x;
    int bb = blockIdx.y;
    int e0 = blockIdx.x * TE;
    if (tid < TE) su[tid] = unpool[e0 + tid];
    const float* skb = skip + (size_t)bb * C * Eout;
    for (int i = tid; i < C * TE; i += 256) {
        int c = i >> 5, e = i & 31;
        ssk[c][e] = skb[(size_t)c * Eout + e0 + e];
    }
    __syncthreads();
    const float* upb = up + (size_t)bb * Ein * C;
    float* ob = out + ((size_t)bb * Eout + e0) * C;
    for (int i = tid; i < C * TE; i += 256) {
        int el = i / C, c = i % C;
        ob[(size_t)el * C + c] = upb[(size_t)su[el] * C + c] + ssk[c][el];
    }
}

// ---------------------------------------------------------------------------
// finalize: stats -> (mean, rinv)
// ---------------------------------------------------------------------------
__global__ void finalize_stats(const double* __restrict__ stats,
                               float2* __restrict__ mstat, int n, int E)
{
    int i = threadIdx.x;
    if (i >= n) return;
    double invE = 1.0 / (double)E;
    double m = stats[2 * i] * invE;
    double var = stats[2 * i + 1] * invE - m * m;
    mstat[i] = make_float2((float)m, rsqrtf((float)var + 1e-5f));
}

// Final: reads (B,E,8), writes d_out (B,8,E) with norm+relu, smem transpose.
__global__ __launch_bounds__(256) void inorm_apply_final(
    const float* __restrict__ x, int E, const float2* __restrict__ mstat,
    float* __restrict__ out)
{
    __shared__ float sm[256];
    int tid = threadIdx.x;
    int bb = blockIdx.y;
    int e0 = blockIdx.x * 32;
    float2 mr = mstat[bb * 8 + (tid & 7)];
    float v = (x[((size_t)bb * E + e0) * 8 + tid] - mr.x) * mr.y;
    sm[tid] = v > 0.f ? v : 0.f;
    __syncthreads();
    int c = tid >> 5, el = tid & 31;
    out[((size_t)bb * 8 + c) * E + e0 + el] = sm[el * 8 + c];
}

// ---------------------------------------------------------------------------
// Host driver
// ---------------------------------------------------------------------------
extern "C" void kernel_launch(void* const* d_in, const int* in_sizes, int n_in,
                              void* d_out, int out_size)
{
    (void)in_sizes; (void)n_in; (void)out_size;
    const int E0 = 16384, E1 = 32768, E2 = 65536, E3 = 131072;

    const float* fe    = (const float*)d_in[0];
    const float* skip0 = (const float*)d_in[1];
    const float* skip1 = (const float*)d_in[2];
    const float* skip2 = (const float*)d_in[3];
    const int4*  gm0   = (const int4*)d_in[4];
    const int4*  gm1   = (const int4*)d_in[5];
    const int4*  gm2   = (const int4*)d_in[6];
    const int4*  gm3   = (const int4*)d_in[7];
    const int*   up0   = (const int*)d_in[8];
    const int*   up1   = (const int*)d_in[9];
    const int*   up2   = (const int*)d_in[10];
    const float* Wup0 = (const float*)d_in[11]; const float* bup0 = (const float*)d_in[12];
    const float* Wc0  = (const float*)d_in[13]; const float* bc0  = (const float*)d_in[14];
    const float* Wup1 = (const float*)d_in[15]; const float* bup1 = (const float*)d_in[16];
    const float* Wc1  = (const float*)d_in[17]; const float* bc1  = (const float*)d_in[18];
    const float* Wup2 = (const float*)d_in[19]; const float* bup2 = (const float*)d_in[20];
    const float* Wc2  = (const float*)d_in[21]; const float* bc2  = (const float*)d_in[22];
    const float* Wupf = (const float*)d_in[23]; const float* bupf = (const float*)d_in[24];
    const float* Wcf  = (const float*)d_in[25]; const float* bcf  = (const float*)d_in[26];
    float* outp = (float*)d_out;

    float *bufA, *bufB, *bufU, *bufY, *wt; double* stats; float2* mstat;
    __nv_bfloat16 *wb;
    cudaGetSymbolAddress((void**)&bufA, g_bufA);
    cudaGetSymbolAddress((void**)&bufB, g_bufB);
    cudaGetSymbolAddress((void**)&bufU, g_bufU);
    cudaGetSymbolAddress((void**)&bufY, g_bufY);
    cudaGetSymbolAddress((void**)&wt,   g_wt);
    cudaGetSymbolAddress((void**)&wb,   g_wb);
    cudaGetSymbolAddress((void**)&stats, g_stats);
    cudaGetSymbolAddress((void**)&mstat, g_mstat);

    float* Wt_upf = wt + 322560;
    float* Wt_cf  = wt + 323840;

    __nv_bfloat16* Wb_up0 = wb;
    __nv_bfloat16* Wb_c0  = wb + 393216;
    __nv_bfloat16* Wb_up1 = wb + 589824;
    __nv_bfloat16* Wb_c1  = wb + 688128;
    __nv_bfloat16* Wb_up2 = wb + 737280;
    __nv_bfloat16* Wb_c2  = wb + 761856;

    double* stats0 = stats;
    double* stats1 = stats + 512;
    double* stats2 = stats + 768;
    double* statsF = stats + 896;
    float2* mst0 = mstat;
    float2* mst1 = mstat + 256;
    float2* mst2 = mstat + 384;
    float2* mstF = mstat + 448;

    const int SM128 = 4 * 14336 + 2 * 128 * 192 + 2048;   // 108544
    const int SM64  = 4 * 14336 + 2 * 64 * 192 + 2048;    //  83968
    const int SM32  = 4 * 14336 + 2 * 32 * 192 + 2048;    //  71680
    cudaFuncSetAttribute(conv_t<256, 128, false, false>, cudaFuncAttributeMaxDynamicSharedMemorySize, SM128);
    cudaFuncSetAttribute(conv_t<128, 128, false, true>,  cudaFuncAttributeMaxDynamicSharedMemorySize, SM128);
    cudaFuncSetAttribute(conv_t<128, 64, true, false>,   cudaFuncAttributeMaxDynamicSharedMemorySize, SM64);
    cudaFuncSetAttribute(conv_t<64, 64, false, true>,    cudaFuncAttributeMaxDynamicSharedMemorySize, SM64);
    cudaFuncSetAttribute(conv_t<64, 32, true, false>,    cudaFuncAttributeMaxDynamicSharedMemorySize, SM32);
    cudaFuncSetAttribute(conv_t<32, 32, false, true>,    cudaFuncAttributeMaxDynamicSharedMemorySize, SM32);

    // launches: wtrans+zero(0), wbf48(1), xpose(2), conv_t up0(3 = ncu target)
    wtrans_all<<<1267, 256>>>(Wup0, Wc0, Wup1, Wc1, Wup2, Wc2, Wupf, Wcf, wt, stats);
    wbf48<<<3024, 256>>>(Wup0, Wc0, Wup1, Wc1, Wup2, Wc2, wb);
    xpose<<<dim3(E0 / 32, 256 / 32, 2), dim3(32, 8)>>>(fe, bufA, E0, 256);

    // ---- Level 0 ----
    conv_t<256, 128, false, false><<<dim3(E0 / 128, 2), 256, SM128>>>(bufA, gm0, Wb_up0, nullptr, bup0, bufU, nullptr, E0);
    unpool_skip<128><<<dim3(E1 / 32, 2), 256>>>(bufU, up0, skip0, bufY, E1, E0);
    conv_t<128, 128, false, true><<<dim3(E1 / 128, 2), 256, SM128>>>(bufY, gm1, Wb_c0, nullptr, bc0, bufB, stats0, E1);
    finalize_stats<<<1, 256>>>(stats0, mst0, 256, E1);

    // ---- Level 1 ---- (up1 consumes bufB with fused norm+relu)
    conv_t<128, 64, true, false><<<dim3(E1 / 128, 2), 256, SM64>>>(bufB, gm1, Wb_up1, mst0, bup1, bufU, nullptr, E1);
    unpool_skip<64><<<dim3(E2 / 32, 2), 256>>>(bufU, up1, skip1, bufY, E2, E1);
    conv_t<64, 64, false, true><<<dim3(E2 / 128, 2), 256, SM64>>>(bufY, gm2, Wb_c1, nullptr, bc1, bufA, stats1, E2);
    finalize_stats<<<1, 128>>>(stats1, mst1, 128, E2);

    // ---- Level 2 ---- (up2 consumes bufA with fused norm+relu)
    conv_t<64, 32, true, false><<<dim3(E2 / 128, 2), 256, SM32>>>(bufA, gm2, Wb_up2, mst1, bup2, bufU, nullptr, E2);
    unpool_skip<32><<<dim3(E3 / 32, 2), 256>>>(bufU, up2, skip2, bufY, E3, E2);
    conv_t<32, 32, false, true><<<dim3(E3 / 128, 2), 256, SM32>>>(bufY, gm3, Wb_c2, nullptr, bc2, bufB, stats2, E3);
    finalize_stats<<<1, 64>>>(stats2, mst2, 64, E3);

    // ---- Final ---- (upf consumes bufB with fused norm+relu; cf fuses stats)
    conv_small<32, true, false><<<dim3(E3 / 256, 2), 256>>>(bufB, gm3, Wt_upf, mst2, bupf, bufU, nullptr, E3);
    conv_small<8, false, true><<<dim3(E3 / 256, 2), 256>>>(bufU, gm3, Wt_cf, nullptr, bcf, bufY, statsF, E3);
    finalize_stats<<<1, 16>>>(statsF, mstF, 16, E3);
    inorm_apply_final<<<dim3(E3 / 32, 2), 256>>>(bufY, E3, mstF, outp);
}

// round 15
// speedup vs baseline: 1.3681x; 1.3681x over previous
#include <cuda_runtime.h>
#include <cuda_bf16.h>
#include <math.h>
#include <stdint.h>

// ---------------------------------------------------------------------------
// Static device scratch. Activations in (B, E, C) layout: x[(b*E+e)*C + c].
// ---------------------------------------------------------------------------
__device__ float  g_bufA[8388608];
__device__ float  g_bufB[8388608];
__device__ float  g_bufU[4194304];
__device__ float  g_bufY[8388608];
__device__ float  g_wt[400000];      // transposed fp32 weights (conv_small)
__device__ __align__(16) __nv_bfloat16 g_wb[774144];   // fragment-ordered, interleaved {hi0,hi1,lo0,lo1}
__device__ double g_stats[1024];
__device__ float2 g_mstat[512];

__device__ __forceinline__ uint32_t smem_u32(const void* p) {
    uint32_t a;
    asm("{ .reg .u64 t; cvta.to.shared.u64 t, %1; cvt.u32.u64 %0, t; }" : "=r"(a) : "l"(p));
    return a;
}

#define STS32(a, v) \
    asm volatile("st.shared.b32 [%0], %1;" :: "r"(a), "r"(v) : "memory")

#define LDMX4(r, addr) \
    asm volatile("ldmatrix.sync.aligned.m8n8.x4.shared.b16 {%0,%1,%2,%3}, [%4];" \
        : "=r"((r)[0]), "=r"((r)[1]), "=r"((r)[2]), "=r"((r)[3]) : "r"(addr))

#define LDS128(r0, r1, r2, r3, addr) \
    asm volatile("ld.shared.v4.b32 {%0,%1,%2,%3}, [%4];" \
        : "=r"(r0), "=r"(r1), "=r"(r2), "=r"(r3) : "r"(addr))

#define CPASYNC16(saddr, gptr) \
    asm volatile("cp.async.cg.shared.global [%0], [%1], 16;" \
        :: "r"(saddr), "l"(gptr) : "memory")

#define CPCOMMIT() asm volatile("cp.async.commit_group;" ::: "memory")
#define CPWAIT0()  asm volatile("cp.async.wait_group 0;" ::: "memory")

#define MMA16816(d, a, b0, b1) \
    asm volatile("mma.sync.aligned.m16n8k16.row.col.f32.bf16.bf16.f32 " \
        "{%0,%1,%2,%3}, {%4,%5,%6,%7}, {%8,%9}, {%0,%1,%2,%3};" \
        : "+f"((d)[0]), "+f"((d)[1]), "+f"((d)[2]), "+f"((d)[3]) \
        : "r"((a)[0]), "r"((a)[1]), "r"((a)[2]), "r"((a)[3]), "r"(b0), "r"(b1))

__device__ __forceinline__ uint32_t b2u(__nv_bfloat162 h) {
    return *reinterpret_cast<uint32_t*>(&h);
}

// ---------------------------------------------------------------------------
// fp32 weight transpose (conv_small path) + stats zeroing (fused)
// ---------------------------------------------------------------------------
__global__ void wtrans_all(const float* __restrict__ W0, const float* __restrict__ W1,
                           const float* __restrict__ W2, const float* __restrict__ W3,
                           const float* __restrict__ W4, const float* __restrict__ W5,
                           const float* __restrict__ W6, const float* __restrict__ W7,
                           float* __restrict__ wt, double* __restrict__ stats)
{
    int i = blockIdx.x * 256 + threadIdx.x;
    if (i < 1024) stats[i] = 0.0;
    if (i >= 324160) return;
    const int Ks[8]   = {1280, 640, 640, 320, 320, 160, 160, 40};
    const int Cs[8]   = {128, 128, 64, 64, 32, 32, 8, 8};
    const int offs[9] = {0, 163840, 245760, 286720, 307200, 317440, 322560, 323840, 324160};
    const float* Ws[8] = {W0, W1, W2, W3, W4, W5, W6, W7};
    int seg = 0;
    while (i >= offs[seg + 1]) seg++;
    int j = i - offs[seg];
    int K = Ks[seg], C = Cs[seg];
    int k = j / C, o = j % C;
    wt[i] = Ws[seg][(size_t)o * K + k];
}

// ---------------------------------------------------------------------------
// Fragment-ordered bf16 weights, 48-k chunks, packed-6 layout:
// kk = cc*6 + s  (cc = channel-in-chunk 0..7, s = feature 0..5, s=5 is pad).
// uint4 per lane: {hi_reg0, hi_reg1, lo_reg0, lo_reg1};
// uint4 index = ((chunk*(COUT/8) + naG)*3 + ka)*32 + lane.
// kk = ka*16 + (lane%4)*2 + half + rr*8.
// ---------------------------------------------------------------------------
__global__ void wbf48(const float* __restrict__ W0, const float* __restrict__ W1,
                      const float* __restrict__ W2, const float* __restrict__ W3,
                      const float* __restrict__ W4, const float* __restrict__ W5,
                      __nv_bfloat16* __restrict__ wb)
{
    int i = blockIdx.x * 256 + threadIdx.x;
    if (i >= 774144) return;
    const int CINs[6]  = {256, 128, 128, 64, 64, 32};
    const int COUTs[6] = {128, 128, 64, 64, 32, 32};
    const int offs[7]  = {0, 393216, 589824, 688128, 737280, 761856, 774144};
    const float* Ws[6] = {W0, W1, W2, W3, W4, W5};
    int seg = 0;
    while (i >= offs[seg + 1]) seg++;
    int j = i - offs[seg];
    int CIN = CINs[seg], COUT = COUTs[seg];
    int half = j & 1;
    int reg  = (j >> 1) & 3;
    int lane = (j >> 3) & 31;
    int t    = j >> 8;
    int ka   = t % 3;  t /= 3;
    int naG  = t % (COUT / 8);
    int chunk = t / (COUT / 8);
    int rr = reg & 1;
    bool lo = (reg >= 2);
    int n  = naG * 8 + (lane >> 2);
    int kk = ka * 16 + (lane & 3) * 2 + half + rr * 8;   // 0..47
    int cc = kk / 6, s = kk % 6;
    float v = 0.f;
    if (s < 5) {
        int c = chunk * 8 + cc;
        v = Ws[seg][(size_t)n * (CIN * 5) + c * 5 + s];
    }
    __nv_bfloat16 h = __float2bfloat16(v);
    wb[i] = lo ? __float2bfloat16(v - __bfloat162float(h)) : h;
}

// ---------------------------------------------------------------------------
// fe (B, C, E) -> (B, E, C) tiled transpose
// ---------------------------------------------------------------------------
__global__ void xpose(const float* __restrict__ in, float* __restrict__ outT,
                      int E, int C) {
    __shared__ float tile[32][33];
    int bb = blockIdx.z;
    int e0 = blockIdx.x * 32, c0 = blockIdx.y * 32;
    int tx = threadIdx.x, ty = threadIdx.y;          // (32, 8)
    const float* inb = in + (size_t)bb * C * E;
    float* ob = outT + (size_t)bb * E * C;
#pragma unroll
    for (int j = 0; j < 32; j += 8)
        tile[ty + j][tx] = inb[(size_t)(c0 + ty + j) * E + e0 + tx];
    __syncthreads();
#pragma unroll
    for (int j = 0; j < 32; j += 8)
        ob[(size_t)(e0 + ty + j) * C + c0 + tx] = tile[tx][ty + j];
}

// ---------------------------------------------------------------------------
// Tensor-core mesh conv (m16n8k16 bf16 mma.sync), 48-k chunks, packed-6
// A layout: each thread's 6 values (5 real + zero) are 12 contiguous bytes
// -> 3 STS32 per (q, buf). Every byte of the 96B read region is rewritten
// each chunk, so no padding pre-zero is needed.
// A tiles double-buffered + register-prefetched gathers; B tiles double-
// buffered via cp.async staged after the barrier (race-free, R12 protocol).
// ---------------------------------------------------------------------------
template<int CIN, int COUT, bool NORM>
__global__ __launch_bounds__(256, 2) void conv_t(
    const float* __restrict__ x, const int4* __restrict__ gemm,
    const __nv_bfloat16* __restrict__ Wb, const float2* __restrict__ mstat,
    const float* __restrict__ bias, float* __restrict__ out, int E)
{
    constexpr int CHUNKS = CIN / 8;
    constexpr int NA = COUT / 16;
    constexpr int PITCH = 112;
    constexpr int ABUF = 128 * PITCH;
    constexpr int BU4  = COUT * 12;
    constexpr int BBUF = BU4 * 16;

    extern __shared__ char smem_raw[];
    const uint32_t sAU = smem_u32(smem_raw);
    const uint32_t sBU = sAU + 4 * ABUF;
    int4* sIdx = reinterpret_cast<int4*>(smem_raw + 4 * ABUF + 2 * BBUF);

    const int tid = threadIdx.x;
    const int wid = tid >> 5, lane = tid & 31;
    const int wm = wid & 3, wn = wid >> 2;
    const int bb = blockIdx.y;
    const int e0 = blockIdx.x * 128;
    const float* xb = x + (size_t)bb * E * CIN;

    for (int i = tid; i < 128; i += 256) sIdx[i] = gemm[e0 + i];

    const int cc = tid & 7;
    const int elb = tid >> 3;

    float acc[2][NA][4];
#pragma unroll
    for (int ma = 0; ma < 2; ma++)
#pragma unroll
        for (int na = 0; na < NA; na++)
#pragma unroll
            for (int u = 0; u < 4; u++) acc[ma][na][u] = 0.f;

    const uint4* wb4 = reinterpret_cast<const uint4*>(Wb);

    auto stageB = [&](int chunk) {
        const uint32_t dst = sBU + (uint32_t)(chunk & 1) * BBUF;
        const uint4* src = wb4 + (size_t)chunk * BU4;
#pragma unroll
        for (int i = tid; i < BU4; i += 256)
            CPASYNC16(dst + (uint32_t)i * 16, src + i);
        CPCOMMIT();
    };

    stageB(0);

    float g[4][5];
    auto gather = [&](int chunk) {
        const float* xc = xb + chunk * 8 + cc;
        float2 mr = make_float2(0.f, 1.f);
        if constexpr (NORM) mr = mstat[bb * CIN + chunk * 8 + cc];
#pragma unroll
        for (int q = 0; q < 4; q++) {
            int el = elb + 32 * q;
            int4 n = sIdx[el];
            float xe = xc[(size_t)(e0 + el) * CIN];
            float f1 = xc[(size_t)n.x * CIN];
            float f2 = xc[(size_t)n.y * CIN];
            float f3 = xc[(size_t)n.z * CIN];
            float f4 = xc[(size_t)n.w * CIN];
            if constexpr (NORM) {
                xe = fmaxf((xe - mr.x) * mr.y, 0.f);
                f1 = fmaxf((f1 - mr.x) * mr.y, 0.f);
                f2 = fmaxf((f2 - mr.x) * mr.y, 0.f);
                f3 = fmaxf((f3 - mr.x) * mr.y, 0.f);
                f4 = fmaxf((f4 - mr.x) * mr.y, 0.f);
            }
            g[q][0] = xe;
            g[q][1] = f1 + f3;  g[q][2] = f2 + f4;
            g[q][3] = fabsf(f1 - f3);  g[q][4] = fabsf(f2 - f4);
        }
    };

    __syncthreads();   // sIdx ready
    gather(0);

    for (int chunk = 0; chunk < CHUNKS; chunk++) {
        const uint32_t bufHi = sAU + (uint32_t)((chunk & 1) * 2) * ABUF;
        const uint32_t bufLo = bufHi + ABUF;
        // ---- commit prefetched gathers: thread (el, cc) owns bytes
        //      [el*PITCH + cc*12, +12): 6 bf16 = {g0..g4, 0}, 3 STS32 ----
#pragma unroll
        for (int q = 0; q < 4; q++) {
            int el = elb + 32 * q;
            uint32_t base = (uint32_t)el * PITCH + (uint32_t)cc * 12;
            __nv_bfloat16 h0 = __float2bfloat16(g[q][0]);
            __nv_bfloat16 h1 = __float2bfloat16(g[q][1]);
            __nv_bfloat16 h2 = __float2bfloat16(g[q][2]);
            __nv_bfloat16 h3 = __float2bfloat16(g[q][3]);
            __nv_bfloat16 h4 = __float2bfloat16(g[q][4]);
            __nv_bfloat16 z  = __float2bfloat16(0.f);
            float r0 = g[q][0] - __bfloat162float(h0);
            float r1 = g[q][1] - __bfloat162float(h1);
            float r2 = g[q][2] - __bfloat162float(h2);
            float r3 = g[q][3] - __bfloat162float(h3);
            float r4 = g[q][4] - __bfloat162float(h4);
            STS32(bufHi + base,     b2u(__halves2bfloat162(h0, h1)));
            STS32(bufHi + base + 4, b2u(__halves2bfloat162(h2, h3)));
            STS32(bufHi + base + 8, b2u(__halves2bfloat162(h4, z)));
            STS32(bufLo + base,     b2u(__floats2bfloat162_rn(r0, r1)));
            STS32(bufLo + base + 4, b2u(__floats2bfloat162_rn(r2, r3)));
            STS32(bufLo + base + 8, b2u(__floats2bfloat162_rn(r4, 0.f)));
        }
        // ---- B(chunk) landed (committed last iteration / prologue) ----
        CPWAIT0();
        __syncthreads();   // A stores + B visible; mma(chunk-1) done
        if (chunk + 1 < CHUNKS) stageB(chunk + 1);
        if (chunk + 1 < CHUNKS) gather(chunk + 1);
        // ---- ldmatrix + mma (B from smem) ----
        const uint32_t bB = sBU + (uint32_t)(chunk & 1) * BBUF;
#pragma unroll
        for (int ka = 0; ka < 3; ka++) {
            uint32_t ah[2][4], al[2][4];
#pragma unroll
            for (int ma = 0; ma < 2; ma++) {
                uint32_t off = (uint32_t)(wm * 32 + ma * 16 + (lane & 15)) * PITCH
                             + (uint32_t)ka * 32 + ((lane >> 4) * 16);
                LDMX4(ah[ma], bufHi + off);
                LDMX4(al[ma], bufLo + off);
            }
#pragma unroll
            for (int na = 0; na < NA; na++) {
                uint32_t wx, wy, wz, ww;
                LDS128(wx, wy, wz, ww,
                       bB + (uint32_t)(((wn * NA + na) * 3 + ka) * 32 + lane) * 16);
#pragma unroll
                for (int ma = 0; ma < 2; ma++) {
                    MMA16816(acc[ma][na], ah[ma], wx, wy);
                    MMA16816(acc[ma][na], al[ma], wx, wy);
                    MMA16816(acc[ma][na], ah[ma], wz, ww);
                }
            }
        }
    }

    // ---- epilogue: acc + bias -> out ----
    const int rbase = e0 + wm * 32 + (lane >> 2);
#pragma unroll
    for (int ma = 0; ma < 2; ma++) {
#pragma unroll
        for (int na = 0; na < NA; na++) {
            int col = wn * NA * 8 + na * 8 + (lane & 3) * 2;
            float bx = bias[col], by = bias[col + 1];
            int row0 = rbase + ma * 16;
            float* p0 = out + ((size_t)bb * E + row0) * COUT + col;
            float* p1 = p0 + (size_t)8 * COUT;
            *reinterpret_cast<float2*>(p0) =
                make_float2(acc[ma][na][0] + bx, acc[ma][na][1] + by);
            *reinterpret_cast<float2*>(p1) =
                make_float2(acc[ma][na][2] + bx, acc[ma][na][3] + by);
        }
    }
}

// ---------------------------------------------------------------------------
// Small-Cout mesh-conv (COUT = 8), fp32, optional fused inorm+relu on input
// ---------------------------------------------------------------------------
template<int CIN, bool NORM>
__global__ __launch_bounds__(256) void conv_small(
    const float* __restrict__ x, const int4* __restrict__ gemm,
    const float* __restrict__ Wt, const float2* __restrict__ mstat,
    const float* __restrict__ bias, float* __restrict__ out, int E)
{
    constexpr int K = CIN * 5;
    __shared__ float sW[K * 8];
    __shared__ float2 sM[CIN];
    int tid = threadIdx.x;
    int bb = blockIdx.y;
    for (int i = tid; i < K * 8; i += 256) sW[i] = Wt[i];
    if (NORM && tid < CIN) sM[tid] = mstat[bb * CIN + tid];
    float acc[8];
#pragma unroll
    for (int o = 0; o < 8; o++) acc[o] = bias[o];
    __syncthreads();

    int e = blockIdx.x * 256 + tid;
    int4 n = gemm[e];
    const float* xb = x + (size_t)bb * E * CIN;
    const float4* r0 = reinterpret_cast<const float4*>(xb + (size_t)e * CIN);
    const float4* r1 = reinterpret_cast<const float4*>(xb + (size_t)n.x * CIN);
    const float4* r2 = reinterpret_cast<const float4*>(xb + (size_t)n.y * CIN);
    const float4* r3 = reinterpret_cast<const float4*>(xb + (size_t)n.z * CIN);
    const float4* r4 = reinterpret_cast<const float4*>(xb + (size_t)n.w * CIN);

#pragma unroll 2
    for (int c4 = 0; c4 < CIN / 4; c4++) {
        float4 xe = r0[c4], a1 = r1[c4], a2 = r2[c4], a3 = r3[c4], a4 = r4[c4];
#define PROC(COMP, CC)                                                         \
        {                                                                      \
            float xv = xe.COMP, v1 = a1.COMP, v2 = a2.COMP,                    \
                  v3 = a3.COMP, v4 = a4.COMP;                                  \
            if constexpr (NORM) {                                              \
                float2 mm = sM[c4 * 4 + CC];                                   \
                xv = fmaxf((xv - mm.x) * mm.y, 0.f);                           \
                v1 = fmaxf((v1 - mm.x) * mm.y, 0.f);                           \
                v2 = fmaxf((v2 - mm.x) * mm.y, 0.f);                           \
                v3 = fmaxf((v3 - mm.x) * mm.y, 0.f);                           \
                v4 = fmaxf((v4 - mm.x) * mm.y, 0.f);                           \
            }                                                                  \
            float g0 = xv;                                                     \
            float s1 = v1 + v3;                                                \
            float s2 = v2 + v4;                                                \
            float d1 = fabsf(v1 - v3);                                         \
            float d2 = fabsf(v2 - v4);                                         \
            const float* w = &sW[(c4 * 4 + CC) * 5 * 8];                       \
            for (int o = 0; o < 8; o++)                                        \
                acc[o] += g0 * w[o] + s1 * w[8 + o] + s2 * w[16 + o]           \
                        + d1 * w[24 + o] + d2 * w[32 + o];                     \
        }
        PROC(x, 0) PROC(y, 1) PROC(z, 2) PROC(w, 3)
#undef PROC
    }
    float* po = out + ((size_t)bb * E + e) * 8;
    *reinterpret_cast<float4*>(po)     = make_float4(acc[0], acc[1], acc[2], acc[3]);
    *reinterpret_cast<float4*>(po + 4) = make_float4(acc[4], acc[5], acc[6], acc[7]);
}

// ---------------------------------------------------------------------------
// unpool + skip
// ---------------------------------------------------------------------------
template<int C>
__global__ __launch_bounds__(256) void unpool_skip(
    const float* __restrict__ up, const int* __restrict__ unpool,
    const float* __restrict__ skip, float* __restrict__ out,
    int Eout, int Ein)
{
    constexpr int TE = 32;
    __shared__ float ssk[C][TE + 1];
    __shared__ int su[TE];
    int tid = threadIdx.x;
    int bb = blockIdx.y;
    int e0 = blockIdx.x * TE;
    if (tid < TE) su[tid] = unpool[e0 + tid];
    const float* skb = skip + (size_t)bb * C * Eout;
    for (int i = tid; i < C * TE; i += 256) {
        int c = i >> 5, e = i & 31;
        ssk[c][e] = skb[(size_t)c * Eout + e0 + e];
    }
    __syncthreads();
    const float* upb = up + (size_t)bb * Ein * C;
    float* ob = out + ((size_t)bb * Eout + e0) * C;
    for (int i = tid; i < C * TE; i += 256) {
        int el = i / C, c = i % C;
        ob[(size_t)el * C + c] = upb[(size_t)su[el] * C + c] + ssk[c][el];
    }
}

// ---------------------------------------------------------------------------
// Instance norm: partial stats + finalize (R12 versions)
// ---------------------------------------------------------------------------
template<int C, int CHUNK>
__global__ __launch_bounds__(256) void inorm_partial(
    const float* __restrict__ x, int E, double* __restrict__ stats)
{
    constexpr int C4 = C / 4;
    constexpr int ESTEP = 256 / C4;
    __shared__ float rb[256][8];
    int tid = threadIdx.x;
    int c4 = tid % C4, er = tid / C4;
    int bb = blockIdx.z;
    int e0 = blockIdx.x * CHUNK;
    const float4* xb4 = reinterpret_cast<const float4*>(x + ((size_t)bb * E + e0) * C) + c4;
    float s0 = 0, s1 = 0, s2 = 0, s3 = 0, q0 = 0, q1 = 0, q2 = 0, q3 = 0;
    for (int e = er; e < CHUNK; e += ESTEP) {
        float4 v = xb4[(size_t)e * C4];
        s0 += v.x; q0 += v.x * v.x;
        s1 += v.y; q1 += v.y * v.y;
        s2 += v.z; q2 += v.z * v.z;
        s3 += v.w; q3 += v.w * v.w;
    }
    rb[tid][0] = s0; rb[tid][1] = s1; rb[tid][2] = s2; rb[tid][3] = s3;
    rb[tid][4] = q0; rb[tid][5] = q1; rb[tid][6] = q2; rb[tid][7] = q3;
    __syncthreads();
    for (int st = ESTEP / 2; st >= 1; st >>= 1) {
        if (er < st) {
#pragma unroll
            for (int u = 0; u < 8; u++) rb[tid][u] += rb[tid + st * C4][u];
        }
        __syncthreads();
    }
    if (er == 0) {
#pragma unroll
        for (int u = 0; u < 4; u++) {
            atomicAdd(&stats[((size_t)bb * C + c4 * 4 + u) * 2],     (double)rb[tid][u]);
            atomicAdd(&stats[((size_t)bb * C + c4 * 4 + u) * 2 + 1], (double)rb[tid][4 + u]);
        }
    }
}

__global__ void finalize_stats(const double* __restrict__ stats,
                               float2* __restrict__ mstat, int n, int E)
{
    int i = threadIdx.x;
    if (i >= n) return;
    double invE = 1.0 / (double)E;
    double m = stats[2 * i] * invE;
    double var = stats[2 * i + 1] * invE - m * m;
    mstat[i] = make_float2((float)m, rsqrtf((float)var + 1e-5f));
}

// Final: reads (B,E,8), writes d_out (B,8,E) with norm+relu, smem transpose.
__global__ __launch_bounds__(256) void inorm_apply_final(
    const float* __restrict__ x, int E, const float2* __restrict__ mstat,
    float* __restrict__ out)
{
    __shared__ float sm[256];
    int tid = threadIdx.x;
    int bb = blockIdx.y;
    int e0 = blockIdx.x * 32;
    float2 mr = mstat[bb * 8 + (tid & 7)];
    float v = (x[((size_t)bb * E + e0) * 8 + tid] - mr.x) * mr.y;
    sm[tid] = v > 0.f ? v : 0.f;
    __syncthreads();
    int c = tid >> 5, el = tid & 31;
    out[((size_t)bb * 8 + c) * E + e0 + el] = sm[el * 8 + c];
}

// ---------------------------------------------------------------------------
// Host driver
// ---------------------------------------------------------------------------
extern "C" void kernel_launch(void* const* d_in, const int* in_sizes, int n_in,
                              void* d_out, int out_size)
{
    (void)in_sizes; (void)n_in; (void)out_size;
    const int E0 = 16384, E1 = 32768, E2 = 65536, E3 = 131072;

    const float* fe    = (const float*)d_in[0];
    const float* skip0 = (const float*)d_in[1];
    const float* skip1 = (const float*)d_in[2];
    const float* skip2 = (const float*)d_in[3];
    const int4*  gm0   = (const int4*)d_in[4];
    const int4*  gm1   = (const int4*)d_in[5];
    const int4*  gm2   = (const int4*)d_in[6];
    const int4*  gm3   = (const int4*)d_in[7];
    const int*   up0   = (const int*)d_in[8];
    const int*   up1   = (const int*)d_in[9];
    const int*   up2   = (const int*)d_in[10];
    const float* Wup0 = (const float*)d_in[11]; const float* bup0 = (const float*)d_in[12];
    const float* Wc0  = (const float*)d_in[13]; const float* bc0  = (const float*)d_in[14];
    const float* Wup1 = (const float*)d_in[15]; const float* bup1 = (const float*)d_in[16];
    const float* Wc1  = (const float*)d_in[17]; const float* bc1  = (const float*)d_in[18];
    const float* Wup2 = (const float*)d_in[19]; const float* bup2 = (const float*)d_in[20];
    const float* Wc2  = (const float*)d_in[21]; const float* bc2  = (const float*)d_in[22];
    const float* Wupf = (const float*)d_in[23]; const float* bupf = (const float*)d_in[24];
    const float* Wcf  = (const float*)d_in[25]; const float* bcf  = (const float*)d_in[26];
    float* outp = (float*)d_out;

    float *bufA, *bufB, *bufU, *bufY, *wt; double* stats; float2* mstat;
    __nv_bfloat16 *wb;
    cudaGetSymbolAddress((void**)&bufA, g_bufA);
    cudaGetSymbolAddress((void**)&bufB, g_bufB);
    cudaGetSymbolAddress((void**)&bufU, g_bufU);
    cudaGetSymbolAddress((void**)&bufY, g_bufY);
    cudaGetSymbolAddress((void**)&wt,   g_wt);
    cudaGetSymbolAddress((void**)&wb,   g_wb);
    cudaGetSymbolAddress((void**)&stats, g_stats);
    cudaGetSymbolAddress((void**)&mstat, g_mstat);

    float* Wt_upf = wt + 322560;
    float* Wt_cf  = wt + 323840;

    __nv_bfloat16* Wb_up0 = wb;
    __nv_bfloat16* Wb_c0  = wb + 393216;
    __nv_bfloat16* Wb_up1 = wb + 589824;
    __nv_bfloat16* Wb_c1  = wb + 688128;
    __nv_bfloat16* Wb_up2 = wb + 737280;
    __nv_bfloat16* Wb_c2  = wb + 761856;

    double* stats0 = stats;
    double* stats1 = stats + 512;
    double* stats2 = stats + 768;
    double* statsF = stats + 896;
    float2* mst0 = mstat;
    float2* mst1 = mstat + 256;
    float2* mst2 = mstat + 384;
    float2* mstF = mstat + 448;

    const int SM128 = 4 * 14336 + 2 * 128 * 192 + 2048;   // 108544
    const int SM64  = 4 * 14336 + 2 * 64 * 192 + 2048;    //  83968
    const int SM32  = 4 * 14336 + 2 * 32 * 192 + 2048;    //  71680
    cudaFuncSetAttribute(conv_t<256, 128, false>, cudaFuncAttributeMaxDynamicSharedMemorySize, SM128);
    cudaFuncSetAttribute(conv_t<128, 128, false>, cudaFuncAttributeMaxDynamicSharedMemorySize, SM128);
    cudaFuncSetAttribute(conv_t<128, 64, true>,   cudaFuncAttributeMaxDynamicSharedMemorySize, SM64);
    cudaFuncSetAttribute(conv_t<64, 64, false>,   cudaFuncAttributeMaxDynamicSharedMemorySize, SM64);
    cudaFuncSetAttribute(conv_t<64, 32, true>,    cudaFuncAttributeMaxDynamicSharedMemorySize, SM32);
    cudaFuncSetAttribute(conv_t<32, 32, false>,   cudaFuncAttributeMaxDynamicSharedMemorySize, SM32);

    // launches: wtrans+zero(0), wbf48(1), xpose(2), conv_t up0(3 = ncu target)
    wtrans_all<<<1267, 256>>>(Wup0, Wc0, Wup1, Wc1, Wup2, Wc2, Wupf, Wcf, wt, stats);
    wbf48<<<3024, 256>>>(Wup0, Wc0, Wup1, Wc1, Wup2, Wc2, wb);
    xpose<<<dim3(E0 / 32, 256 / 32, 2), dim3(32, 8)>>>(fe, bufA, E0, 256);

    // ---- Level 0 ----
    conv_t<256, 128, false><<<dim3(E0 / 128, 2), 256, SM128>>>(bufA, gm0, Wb_up0, nullptr, bup0, bufU, E0);
    unpool_skip<128><<<dim3(E1 / 32, 2), 256>>>(bufU, up0, skip0, bufY, E1, E0);
    conv_t<128, 128, false><<<dim3(E1 / 128, 2), 256, SM128>>>(bufY, gm1, Wb_c0, nullptr, bc0, bufB, E1);
    inorm_partial<128, 256><<<dim3(E1 / 256, 1, 2), 256>>>(bufB, E1, stats0);
    finalize_stats<<<1, 256>>>(stats0, mst0, 256, E1);

    // ---- Level 1 ---- (up1 consumes bufB with fused norm+relu)
    conv_t<128, 64, true><<<dim3(E1 / 128, 2), 256, SM64>>>(bufB, gm1, Wb_up1, mst0, bup1, bufU, E1);
    unpool_skip<64><<<dim3(E2 / 32, 2), 256>>>(bufU, up1, skip1, bufY, E2, E1);
    conv_t<64, 64, false><<<dim3(E2 / 128, 2), 256, SM64>>>(bufY, gm2, Wb_c1, nullptr, bc1, bufA, E2);
    inorm_partial<64, 512><<<dim3(E2 / 512, 1, 2), 256>>>(bufA, E2, stats1);
    finalize_stats<<<1, 128>>>(stats1, mst1, 128, E2);

    // ---- Level 2 ---- (up2 consumes bufA with fused norm+relu)
    conv_t<64, 32, true><<<dim3(E2 / 128, 2), 256, SM32>>>(bufA, gm2, Wb_up2, mst1, bup2, bufU, E2);
    unpool_skip<32><<<dim3(E3 / 32, 2), 256>>>(bufU, up2, skip2, bufY, E3, E2);
    conv_t<32, 32, false><<<dim3(E3 / 128, 2), 256, SM32>>>(bufY, gm3, Wb_c2, nullptr, bc2, bufB, E3);
    inorm_partial<32, 1024><<<dim3(E3 / 1024, 1, 2), 256>>>(bufB, E3, stats2);
    finalize_stats<<<1, 64>>>(stats2, mst2, 64, E3);

    // ---- Final ---- (upf consumes bufB with fused norm+relu)
    conv_small<32, true><<<dim3(E3 / 256, 2), 256>>>(bufB, gm3, Wt_upf, mst2, bupf, bufU, E3);
    conv_small<8, false><<<dim3(E3 / 256, 2), 256>>>(bufU, gm3, Wt_cf, nullptr, bcf, bufY, E3);
    inorm_partial<8, 4096><<<dim3(E3 / 4096, 1, 2), 256>>>(bufY, E3, statsF);
    finalize_stats<<<1, 16>>>(statsF, mstF, 16, E3);
    inorm_apply_final<<<dim3(E3 / 32, 2), 256>>>(bufY, E3, mstF, outp);
}

// round 16
// speedup vs baseline: 1.5620x; 1.1417x over previous
#include <cuda_runtime.h>
#include <cuda_bf16.h>
#include <cuda_fp16.h>
#include <math.h>
#include <stdint.h>

// ---------------------------------------------------------------------------
// Static device scratch. Activations in (B, E, C) layout: x[(b*E+e)*C + c].
// ---------------------------------------------------------------------------
__device__ float  g_bufA[8388608];
__device__ float  g_bufB[8388608];
__device__ float  g_bufU[4194304];
__device__ float  g_bufY[8388608];
__device__ float  g_wt[400000];      // transposed fp32 weights (conv_small)
__device__ __align__(16) __nv_bfloat16 g_wb[774144];   // bf16 {hi0,hi1,lo0,lo1} frags
__device__ __align__(16) __half g_wh[294912];          // fp16 hi-only frags (up0, c0)
__device__ double g_stats[1024];
__device__ float2 g_mstat[512];

__device__ __forceinline__ uint32_t smem_u32(const void* p) {
    uint32_t a;
    asm("{ .reg .u64 t; cvta.to.shared.u64 t, %1; cvt.u32.u64 %0, t; }" : "=r"(a) : "l"(p));
    return a;
}

#define STS32(a, v) \
    asm volatile("st.shared.b32 [%0], %1;" :: "r"(a), "r"(v) : "memory")

#define LDMX4(r, addr) \
    asm volatile("ldmatrix.sync.aligned.m8n8.x4.shared.b16 {%0,%1,%2,%3}, [%4];" \
        : "=r"((r)[0]), "=r"((r)[1]), "=r"((r)[2]), "=r"((r)[3]) : "r"(addr))

#define LDS128(r0, r1, r2, r3, addr) \
    asm volatile("ld.shared.v4.b32 {%0,%1,%2,%3}, [%4];" \
        : "=r"(r0), "=r"(r1), "=r"(r2), "=r"(r3) : "r"(addr))

#define LDS64(r0, r1, addr) \
    asm volatile("ld.shared.v2.b32 {%0,%1}, [%2];" \
        : "=r"(r0), "=r"(r1) : "r"(addr))

#define CPASYNC16(saddr, gptr) \
    asm volatile("cp.async.cg.shared.global [%0], [%1], 16;" \
        :: "r"(saddr), "l"(gptr) : "memory")

#define CPCOMMIT() asm volatile("cp.async.commit_group;" ::: "memory")
#define CPWAIT0()  asm volatile("cp.async.wait_group 0;" ::: "memory")

#define MMA16816(d, a, b0, b1) \
    asm volatile("mma.sync.aligned.m16n8k16.row.col.f32.bf16.bf16.f32 " \
        "{%0,%1,%2,%3}, {%4,%5,%6,%7}, {%8,%9}, {%0,%1,%2,%3};" \
        : "+f"((d)[0]), "+f"((d)[1]), "+f"((d)[2]), "+f"((d)[3]) \
        : "r"((a)[0]), "r"((a)[1]), "r"((a)[2]), "r"((a)[3]), "r"(b0), "r"(b1))

#define MMA16816H(d, a, b0, b1) \
    asm volatile("mma.sync.aligned.m16n8k16.row.col.f32.f16.f16.f32 " \
        "{%0,%1,%2,%3}, {%4,%5,%6,%7}, {%8,%9}, {%0,%1,%2,%3};" \
        : "+f"((d)[0]), "+f"((d)[1]), "+f"((d)[2]), "+f"((d)[3]) \
        : "r"((a)[0]), "r"((a)[1]), "r"((a)[2]), "r"((a)[3]), "r"(b0), "r"(b1))

__device__ __forceinline__ uint32_t b2u(__nv_bfloat162 h) {
    return *reinterpret_cast<uint32_t*>(&h);
}
__device__ __forceinline__ uint32_t h2u(__half2 h) {
    return *reinterpret_cast<uint32_t*>(&h);
}

// ---------------------------------------------------------------------------
// fp32 weight transpose (conv_small path) + stats zeroing (fused)
// ---------------------------------------------------------------------------
__global__ void wtrans_all(const float* __restrict__ W0, const float* __restrict__ W1,
                           const float* __restrict__ W2, const float* __restrict__ W3,
                           const float* __restrict__ W4, const float* __restrict__ W5,
                           const float* __restrict__ W6, const float* __restrict__ W7,
                           float* __restrict__ wt, double* __restrict__ stats)
{
    int i = blockIdx.x * 256 + threadIdx.x;
    if (i < 1024) stats[i] = 0.0;
    if (i >= 324160) return;
    const int Ks[8]   = {1280, 640, 640, 320, 320, 160, 160, 40};
    const int Cs[8]   = {128, 128, 64, 64, 32, 32, 8, 8};
    const int offs[9] = {0, 163840, 245760, 286720, 307200, 317440, 322560, 323840, 324160};
    const float* Ws[8] = {W0, W1, W2, W3, W4, W5, W6, W7};
    int seg = 0;
    while (i >= offs[seg + 1]) seg++;
    int j = i - offs[seg];
    int K = Ks[seg], C = Cs[seg];
    int k = j / C, o = j % C;
    wt[i] = Ws[seg][(size_t)o * K + k];
}

// ---------------------------------------------------------------------------
// Fragment-ordered weights, 48-k chunks, packed-6 layout (kk = cc*6 + s,
// s=5 is pad). bf16 part (all 6 convs): uint4/lane {hi0,hi1,lo0,lo1},
// uint4 idx = ((chunk*(COUT/8)+naG)*3+ka)*32+lane; kk = ka*16+(lane%4)*2+half+rr*8.
// fp16 part (up0, c0 only, hi-only): uint2/lane {reg0,reg1},
// element j2 = (((chunk*16+naG)*3+ka)*32+lane)*4 + reg*2 + half.
// ---------------------------------------------------------------------------
__global__ void wbf48(const float* __restrict__ W0, const float* __restrict__ W1,
                      const float* __restrict__ W2, const float* __restrict__ W3,
                      const float* __restrict__ W4, const float* __restrict__ W5,
                      __nv_bfloat16* __restrict__ wb, __half* __restrict__ wh)
{
    int i = blockIdx.x * 256 + threadIdx.x;
    if (i >= 1069056) return;
    if (i >= 774144) {
        // fp16 hi-only tables: seg0 = up0 (CIN=256), seg1 = c0 (CIN=128)
        int j2 = i - 774144;
        const float* W = (j2 < 196608) ? W0 : W1;
        int CIN = (j2 < 196608) ? 256 : 128;
        int jj = (j2 < 196608) ? j2 : j2 - 196608;
        int half = jj & 1;
        int reg  = (jj >> 1) & 1;
        int lane = (jj >> 2) & 31;
        int t    = jj >> 7;
        int ka   = t % 3;  t /= 3;
        int naG  = t % 16;
        int chunk = t / 16;
        int n  = naG * 8 + (lane >> 2);
        int kk = ka * 16 + (lane & 3) * 2 + half + reg * 8;
        int cc = kk / 6, s = kk % 6;
        float v = 0.f;
        if (s < 5) v = W[(size_t)n * (CIN * 5) + (chunk * 8 + cc) * 5 + s];
        wh[j2] = __float2half_rn(v);
        return;
    }
    const int CINs[6]  = {256, 128, 128, 64, 64, 32};
    const int COUTs[6] = {128, 128, 64, 64, 32, 32};
    const int offs[7]  = {0, 393216, 589824, 688128, 737280, 761856, 774144};
    const float* Ws[6] = {W0, W1, W2, W3, W4, W5};
    int seg = 0;
    while (i >= offs[seg + 1]) seg++;
    int j = i - offs[seg];
    int CIN = CINs[seg], COUT = COUTs[seg];
    int half = j & 1;
    int reg  = (j >> 1) & 3;
    int lane = (j >> 3) & 31;
    int t    = j >> 8;
    int ka   = t % 3;  t /= 3;
    int naG  = t % (COUT / 8);
    int chunk = t / (COUT / 8);
    int rr = reg & 1;
    bool lo = (reg >= 2);
    int n  = naG * 8 + (lane >> 2);
    int kk = ka * 16 + (lane & 3) * 2 + half + rr * 8;
    int cc = kk / 6, s = kk % 6;
    float v = 0.f;
    if (s < 5) v = Ws[seg][(size_t)n * (CIN * 5) + (chunk * 8 + cc) * 5 + s];
    __nv_bfloat16 h = __float2bfloat16(v);
    wb[i] = lo ? __float2bfloat16(v - __bfloat162float(h)) : h;
}

// ---------------------------------------------------------------------------
// fe (B, C, E) -> (B, E, C) tiled transpose
// ---------------------------------------------------------------------------
__global__ void xpose(const float* __restrict__ in, float* __restrict__ outT,
                      int E, int C) {
    __shared__ float tile[32][33];
    int bb = blockIdx.z;
    int e0 = blockIdx.x * 32, c0 = blockIdx.y * 32;
    int tx = threadIdx.x, ty = threadIdx.y;          // (32, 8)
    const float* inb = in + (size_t)bb * C * E;
    float* ob = outT + (size_t)bb * E * C;
#pragma unroll
    for (int j = 0; j < 32; j += 8)
        tile[ty + j][tx] = inb[(size_t)(c0 + ty + j) * E + e0 + tx];
    __syncthreads();
#pragma unroll
    for (int j = 0; j < 32; j += 8)
        ob[(size_t)(e0 + ty + j) * C + c0 + tx] = tile[tx][ty + j];
}

// ---------------------------------------------------------------------------
// bf16 3-term tensor-core mesh conv (R15 pipeline, packed-6 A layout).
// ---------------------------------------------------------------------------
template<int CIN, int COUT, bool NORM>
__global__ __launch_bounds__(256, 2) void conv_t(
    const float* __restrict__ x, const int4* __restrict__ gemm,
    const __nv_bfloat16* __restrict__ Wb, const float2* __restrict__ mstat,
    const float* __restrict__ bias, float* __restrict__ out, int E)
{
    constexpr int CHUNKS = CIN / 8;
    constexpr int NA = COUT / 16;
    constexpr int PITCH = 112;
    constexpr int ABUF = 128 * PITCH;
    constexpr int BU4  = COUT * 12;
    constexpr int BBUF = BU4 * 16;

    extern __shared__ char smem_raw[];
    const uint32_t sAU = smem_u32(smem_raw);
    const uint32_t sBU = sAU + 4 * ABUF;
    int4* sIdx = reinterpret_cast<int4*>(smem_raw + 4 * ABUF + 2 * BBUF);

    const int tid = threadIdx.x;
    const int wid = tid >> 5, lane = tid & 31;
    const int wm = wid & 3, wn = wid >> 2;
    const int bb = blockIdx.y;
    const int e0 = blockIdx.x * 128;
    const float* xb = x + (size_t)bb * E * CIN;

    for (int i = tid; i < 128; i += 256) sIdx[i] = gemm[e0 + i];

    const int cc = tid & 7;
    const int elb = tid >> 3;

    float acc[2][NA][4];
#pragma unroll
    for (int ma = 0; ma < 2; ma++)
#pragma unroll
        for (int na = 0; na < NA; na++)
#pragma unroll
            for (int u = 0; u < 4; u++) acc[ma][na][u] = 0.f;

    const uint4* wb4 = reinterpret_cast<const uint4*>(Wb);

    auto stageB = [&](int chunk) {
        const uint32_t dst = sBU + (uint32_t)(chunk & 1) * BBUF;
        const uint4* src = wb4 + (size_t)chunk * BU4;
#pragma unroll
        for (int i = tid; i < BU4; i += 256)
            CPASYNC16(dst + (uint32_t)i * 16, src + i);
        CPCOMMIT();
    };

    stageB(0);

    float g[4][5];
    auto gather = [&](int chunk) {
        const float* xc = xb + chunk * 8 + cc;
        float2 mr = make_float2(0.f, 1.f);
        if constexpr (NORM) mr = mstat[bb * CIN + chunk * 8 + cc];
#pragma unroll
        for (int q = 0; q < 4; q++) {
            int el = elb + 32 * q;
            int4 n = sIdx[el];
            float xe = xc[(size_t)(e0 + el) * CIN];
            float f1 = xc[(size_t)n.x * CIN];
            float f2 = xc[(size_t)n.y * CIN];
            float f3 = xc[(size_t)n.z * CIN];
            float f4 = xc[(size_t)n.w * CIN];
            if constexpr (NORM) {
                xe = fmaxf((xe - mr.x) * mr.y, 0.f);
                f1 = fmaxf((f1 - mr.x) * mr.y, 0.f);
                f2 = fmaxf((f2 - mr.x) * mr.y, 0.f);
                f3 = fmaxf((f3 - mr.x) * mr.y, 0.f);
                f4 = fmaxf((f4 - mr.x) * mr.y, 0.f);
            }
            g[q][0] = xe;
            g[q][1] = f1 + f3;  g[q][2] = f2 + f4;
            g[q][3] = fabsf(f1 - f3);  g[q][4] = fabsf(f2 - f4);
        }
    };

    __syncthreads();
    gather(0);

    for (int chunk = 0; chunk < CHUNKS; chunk++) {
        const uint32_t bufHi = sAU + (uint32_t)((chunk & 1) * 2) * ABUF;
        const uint32_t bufLo = bufHi + ABUF;
#pragma unroll
        for (int q = 0; q < 4; q++) {
            int el = elb + 32 * q;
            uint32_t base = (uint32_t)el * PITCH + (uint32_t)cc * 12;
            __nv_bfloat16 h0 = __float2bfloat16(g[q][0]);
            __nv_bfloat16 h1 = __float2bfloat16(g[q][1]);
            __nv_bfloat16 h2 = __float2bfloat16(g[q][2]);
            __nv_bfloat16 h3 = __float2bfloat16(g[q][3]);
            __nv_bfloat16 h4 = __float2bfloat16(g[q][4]);
            __nv_bfloat16 z  = __float2bfloat16(0.f);
            float r0 = g[q][0] - __bfloat162float(h0);
            float r1 = g[q][1] - __bfloat162float(h1);
            float r2 = g[q][2] - __bfloat162float(h2);
            float r3 = g[q][3] - __bfloat162float(h3);
            float r4 = g[q][4] - __bfloat162float(h4);
            STS32(bufHi + base,     b2u(__halves2bfloat162(h0, h1)));
            STS32(bufHi + base + 4, b2u(__halves2bfloat162(h2, h3)));
            STS32(bufHi + base + 8, b2u(__halves2bfloat162(h4, z)));
            STS32(bufLo + base,     b2u(__floats2bfloat162_rn(r0, r1)));
            STS32(bufLo + base + 4, b2u(__floats2bfloat162_rn(r2, r3)));
            STS32(bufLo + base + 8, b2u(__floats2bfloat162_rn(r4, 0.f)));
        }
        CPWAIT0();
        __syncthreads();
        if (chunk + 1 < CHUNKS) stageB(chunk + 1);
        if (chunk + 1 < CHUNKS) gather(chunk + 1);
        const uint32_t bB = sBU + (uint32_t)(chunk & 1) * BBUF;
#pragma unroll
        for (int ka = 0; ka < 3; ka++) {
            uint32_t ah[2][4], al[2][4];
#pragma unroll
            for (int ma = 0; ma < 2; ma++) {
                uint32_t off = (uint32_t)(wm * 32 + ma * 16 + (lane & 15)) * PITCH
                             + (uint32_t)ka * 32 + ((lane >> 4) * 16);
                LDMX4(ah[ma], bufHi + off);
                LDMX4(al[ma], bufLo + off);
            }
#pragma unroll
            for (int na = 0; na < NA; na++) {
                uint32_t wx, wy, wz, ww;
                LDS128(wx, wy, wz, ww,
                       bB + (uint32_t)(((wn * NA + na) * 3 + ka) * 32 + lane) * 16);
#pragma unroll
                for (int ma = 0; ma < 2; ma++) {
                    MMA16816(acc[ma][na], ah[ma], wx, wy);
                    MMA16816(acc[ma][na], al[ma], wx, wy);
                    MMA16816(acc[ma][na], ah[ma], wz, ww);
                }
            }
        }
    }

    const int rbase = e0 + wm * 32 + (lane >> 2);
#pragma unroll
    for (int ma = 0; ma < 2; ma++) {
#pragma unroll
        for (int na = 0; na < NA; na++) {
            int col = wn * NA * 8 + na * 8 + (lane & 3) * 2;
            float bx = bias[col], by = bias[col + 1];
            int row0 = rbase + ma * 16;
            float* p0 = out + ((size_t)bb * E + row0) * COUT + col;
            float* p1 = p0 + (size_t)8 * COUT;
            *reinterpret_cast<float2*>(p0) =
                make_float2(acc[ma][na][0] + bx, acc[ma][na][1] + by);
            *reinterpret_cast<float2*>(p1) =
                make_float2(acc[ma][na][2] + bx, acc[ma][na][3] + by);
        }
    }
}

// ---------------------------------------------------------------------------
// fp16 2-term tensor-core mesh conv (COUT=128, no NORM): A split hi/lo fp16,
// B hi-only fp16. acc = AhBh + AlBh (W-residual term dropped; rel err ~2^-11).
// 6 MMAs/chunk-ka-na-ma pair group vs 9 in the bf16 path.
// ---------------------------------------------------------------------------
template<int CIN>
__global__ __launch_bounds__(256, 2) void conv_t2(
    const float* __restrict__ x, const int4* __restrict__ gemm,
    const __half* __restrict__ Wh,
    const float* __restrict__ bias, float* __restrict__ out, int E)
{
    constexpr int COUT = 128;
    constexpr int CHUNKS = CIN / 8;
    constexpr int NA = COUT / 16;       // 8
    constexpr int PITCH = 112;
    constexpr int ABUF = 128 * PITCH;
    constexpr int BU4  = COUT * 6;      // uint4 per B chunk (COUT*96B/16)
    constexpr int BBUF = BU4 * 16;      // COUT*96

    extern __shared__ char smem_raw[];
    const uint32_t sAU = smem_u32(smem_raw);
    const uint32_t sBU = sAU + 4 * ABUF;
    int4* sIdx = reinterpret_cast<int4*>(smem_raw + 4 * ABUF + 2 * BBUF);

    const int tid = threadIdx.x;
    const int wid = tid >> 5, lane = tid & 31;
    const int wm = wid & 3, wn = wid >> 2;
    const int bb = blockIdx.y;
    const int e0 = blockIdx.x * 128;
    const float* xb = x + (size_t)bb * E * CIN;

    for (int i = tid; i < 128; i += 256) sIdx[i] = gemm[e0 + i];

    const int cc = tid & 7;
    const int elb = tid >> 3;

    float acc[2][NA][4];
#pragma unroll
    for (int ma = 0; ma < 2; ma++)
#pragma unroll
        for (int na = 0; na < NA; na++)
#pragma unroll
            for (int u = 0; u < 4; u++) acc[ma][na][u] = 0.f;

    const uint4* wh4 = reinterpret_cast<const uint4*>(Wh);

    auto stageB = [&](int chunk) {
        const uint32_t dst = sBU + (uint32_t)(chunk & 1) * BBUF;
        const uint4* src = wh4 + (size_t)chunk * BU4;
#pragma unroll
        for (int i = tid; i < BU4; i += 256)
            CPASYNC16(dst + (uint32_t)i * 16, src + i);
        CPCOMMIT();
    };

    stageB(0);

    float g[4][5];
    auto gather = [&](int chunk) {
        const float* xc = xb + chunk * 8 + cc;
#pragma unroll
        for (int q = 0; q < 4; q++) {
            int el = elb + 32 * q;
            int4 n = sIdx[el];
            float xe = xc[(size_t)(e0 + el) * CIN];
            float f1 = xc[(size_t)n.x * CIN];
            float f2 = xc[(size_t)n.y * CIN];
            float f3 = xc[(size_t)n.z * CIN];
            float f4 = xc[(size_t)n.w * CIN];
            g[q][0] = xe;
            g[q][1] = f1 + f3;  g[q][2] = f2 + f4;
            g[q][3] = fabsf(f1 - f3);  g[q][4] = fabsf(f2 - f4);
        }
    };

    __syncthreads();
    gather(0);

    for (int chunk = 0; chunk < CHUNKS; chunk++) {
        const uint32_t bufHi = sAU + (uint32_t)((chunk & 1) * 2) * ABUF;
        const uint32_t bufLo = bufHi + ABUF;
#pragma unroll
        for (int q = 0; q < 4; q++) {
            int el = elb + 32 * q;
            uint32_t base = (uint32_t)el * PITCH + (uint32_t)cc * 12;
            __half h0 = __float2half_rn(g[q][0]);
            __half h1 = __float2half_rn(g[q][1]);
            __half h2 = __float2half_rn(g[q][2]);
            __half h3 = __float2half_rn(g[q][3]);
            __half h4 = __float2half_rn(g[q][4]);
            __half z  = __float2half_rn(0.f);
            __half r0 = __float2half_rn(g[q][0] - __half2float(h0));
            __half r1 = __float2half_rn(g[q][1] - __half2float(h1));
            __half r2 = __float2half_rn(g[q][2] - __half2float(h2));
            __half r3 = __float2half_rn(g[q][3] - __half2float(h3));
            __half r4 = __float2half_rn(g[q][4] - __half2float(h4));
            STS32(bufHi + base,     h2u(__halves2half2(h0, h1)));
            STS32(bufHi + base + 4, h2u(__halves2half2(h2, h3)));
            STS32(bufHi + base + 8, h2u(__halves2half2(h4, z)));
            STS32(bufLo + base,     h2u(__halves2half2(r0, r1)));
            STS32(bufLo + base + 4, h2u(__halves2half2(r2, r3)));
            STS32(bufLo + base + 8, h2u(__halves2half2(r4, z)));
        }
        CPWAIT0();
        __syncthreads();
        if (chunk + 1 < CHUNKS) stageB(chunk + 1);
        if (chunk + 1 < CHUNKS) gather(chunk + 1);
        const uint32_t bB = sBU + (uint32_t)(chunk & 1) * BBUF;
#pragma unroll
        for (int ka = 0; ka < 3; ka++) {
            uint32_t ah[2][4], al[2][4];
#pragma unroll
            for (int ma = 0; ma < 2; ma++) {
                uint32_t off = (uint32_t)(wm * 32 + ma * 16 + (lane & 15)) * PITCH
                             + (uint32_t)ka * 32 + ((lane >> 4) * 16);
                LDMX4(ah[ma], bufHi + off);
                LDMX4(al[ma], bufLo + off);
            }
#pragma unroll
            for (int na = 0; na < NA; na++) {
                uint32_t wx, wy;
                LDS64(wx, wy,
                      bB + (uint32_t)(((wn * NA + na) * 3 + ka) * 32 + lane) * 8);
#pragma unroll
                for (int ma = 0; ma < 2; ma++) {
                    MMA16816H(acc[ma][na], ah[ma], wx, wy);
                    MMA16816H(acc[ma][na], al[ma], wx, wy);
                }
            }
        }
    }

    const int rbase = e0 + wm * 32 + (lane >> 2);
#pragma unroll
    for (int ma = 0; ma < 2; ma++) {
#pragma unroll
        for (int na = 0; na < NA; na++) {
            int col = wn * NA * 8 + na * 8 + (lane & 3) * 2;
            float bx = bias[col], by = bias[col + 1];
            int row0 = rbase + ma * 16;
            float* p0 = out + ((size_t)bb * E + row0) * COUT + col;
            float* p1 = p0 + (size_t)8 * COUT;
            *reinterpret_cast<float2*>(p0) =
                make_float2(acc[ma][na][0] + bx, acc[ma][na][1] + by);
            *reinterpret_cast<float2*>(p1) =
                make_float2(acc[ma][na][2] + bx, acc[ma][na][3] + by);
        }
    }
}

// ---------------------------------------------------------------------------
// Small-Cout mesh-conv (COUT = 8), fp32, optional fused inorm+relu on input
// ---------------------------------------------------------------------------
template<int CIN, bool NORM>
__global__ __launch_bounds__(256) void conv_small(
    const float* __restrict__ x, const int4* __restrict__ gemm,
    const float* __restrict__ Wt, const float2* __restrict__ mstat,
    const float* __restrict__ bias, float* __restrict__ out, int E)
{
    constexpr int K = CIN * 5;
    __shared__ float sW[K * 8];
    __shared__ float2 sM[CIN];
    int tid = threadIdx.x;
    int bb = blockIdx.y;
    for (int i = tid; i < K * 8; i += 256) sW[i] = Wt[i];
    if (NORM && tid < CIN) sM[tid] = mstat[bb * CIN + tid];
    float acc[8];
#pragma unroll
    for (int o = 0; o < 8; o++) acc[o] = bias[o];
    __syncthreads();

    int e = blockIdx.x * 256 + tid;
    int4 n = gemm[e];
    const float* xb = x + (size_t)bb * E * CIN;
    const float4* r0 = reinterpret_cast<const float4*>(xb + (size_t)e * CIN);
    const float4* r1 = reinterpret_cast<const float4*>(xb + (size_t)n.x * CIN);
    const float4* r2 = reinterpret_cast<const float4*>(xb + (size_t)n.y * CIN);
    const float4* r3 = reinterpret_cast<const float4*>(xb + (size_t)n.z * CIN);
    const float4* r4 = reinterpret_cast<const float4*>(xb + (size_t)n.w * CIN);

#pragma unroll 2
    for (int c4 = 0; c4 < CIN / 4; c4++) {
        float4 xe = r0[c4], a1 = r1[c4], a2 = r2[c4], a3 = r3[c4], a4 = r4[c4];
#define PROC(COMP, CC)                                                         \
        {                                                                      \
            float xv = xe.COMP, v1 = a1.COMP, v2 = a2.COMP,                    \
                  v3 = a3.COMP, v4 = a4.COMP;                                  \
            if constexpr (NORM) {                                              \
                float2 mm = sM[c4 * 4 + CC];                                   \
                xv = fmaxf((xv - mm.x) * mm.y, 0.f);                           \
                v1 = fmaxf((v1 - mm.x) * mm.y, 0.f);                           \
                v2 = fmaxf((v2 - mm.x) * mm.y, 0.f);                           \
                v3 = fmaxf((v3 - mm.x) * mm.y, 0.f);                           \
                v4 = fmaxf((v4 - mm.x) * mm.y, 0.f);                           \
            }                                                                  \
            float g0 = xv;                                                     \
            float s1 = v1 + v3;                                                \
            float s2 = v2 + v4;                                                \
            float d1 = fabsf(v1 - v3);                                         \
            float d2 = fabsf(v2 - v4);                                         \
            const float* w = &sW[(c4 * 4 + CC) * 5 * 8];                       \
            for (int o = 0; o < 8; o++)                                        \
                acc[o] += g0 * w[o] + s1 * w[8 + o] + s2 * w[16 + o]           \
                        + d1 * w[24 + o] + d2 * w[32 + o];                     \
        }
        PROC(x, 0) PROC(y, 1) PROC(z, 2) PROC(w, 3)
#undef PROC
    }
    float* po = out + ((size_t)bb * E + e) * 8;
    *reinterpret_cast<float4*>(po)     = make_float4(acc[0], acc[1], acc[2], acc[3]);
    *reinterpret_cast<float4*>(po + 4) = make_float4(acc[4], acc[5], acc[6], acc[7]);
}

// ---------------------------------------------------------------------------
// unpool + skip
// ---------------------------------------------------------------------------
template<int C>
__global__ __launch_bounds__(256) void unpool_skip(
    const float* __restrict__ up, const int* __restrict__ unpool,
    const float* __restrict__ skip, float* __restrict__ out,
    int Eout, int Ein)
{
    constexpr int TE = 32;
    __shared__ float ssk[C][TE + 1];
    __shared__ int su[TE];
    int tid = threadIdx.x;
    int bb = blockIdx.y;
    int e0 = blockIdx.x * TE;
    if (tid < TE) su[tid] = unpool[e0 + tid];
    const float* skb = skip + (size_t)bb * C * Eout;
    for (int i = tid; i < C * TE; i += 256) {
        int c = i >> 5, e = i & 31;
        ssk[c][e] = skb[(size_t)c * Eout + e0 + e];
    }
    __syncthreads();
    const float* upb = up + (size_t)bb * Ein * C;
    float* ob = out + ((size_t)bb * Eout + e0) * C;
    for (int i = tid; i < C * TE; i += 256) {
        int el = i / C, c = i % C;
        ob[(size_t)el * C + c] = upb[(size_t)su[el] * C + c] + ssk[c][el];
    }
}

// ---------------------------------------------------------------------------
// Instance norm: partial stats + finalize
// ---------------------------------------------------------------------------
template<int C, int CHUNK>
__global__ __launch_bounds__(256) void inorm_partial(
    const float* __restrict__ x, int E, double* __restrict__ stats)
{
    constexpr int C4 = C / 4;
    constexpr int ESTEP = 256 / C4;
    __shared__ float rb[256][8];
    int tid = threadIdx.x;
    int c4 = tid % C4, er = tid / C4;
    int bb = blockIdx.z;
    int e0 = blockIdx.x * CHUNK;
    const float4* xb4 = reinterpret_cast<const float4*>(x + ((size_t)bb * E + e0) * C) + c4;
    float s0 = 0, s1 = 0, s2 = 0, s3 = 0, q0 = 0, q1 = 0, q2 = 0, q3 = 0;
    for (int e = er; e < CHUNK; e += ESTEP) {
        float4 v = xb4[(size_t)e * C4];
        s0 += v.x; q0 += v.x * v.x;
        s1 += v.y; q1 += v.y * v.y;
        s2 += v.z; q2 += v.z * v.z;
        s3 += v.w; q3 += v.w * v.w;
    }
    rb[tid][0] = s0; rb[tid][1] = s1; rb[tid][2] = s2; rb[tid][3] = s3;
    rb[tid][4] = q0; rb[tid][5] = q1; rb[tid][6] = q2; rb[tid][7] = q3;
    __syncthreads();
    for (int st = ESTEP / 2; st >= 1; st >>= 1) {
        if (er < st) {
#pragma unroll
            for (int u = 0; u < 8; u++) rb[tid][u] += rb[tid + st * C4][u];
        }
        __syncthreads();
    }
    if (er == 0) {
#pragma unroll
        for (int u = 0; u < 4; u++) {
            atomicAdd(&stats[((size_t)bb * C + c4 * 4 + u) * 2],     (double)rb[tid][u]);
            atomicAdd(&stats[((size_t)bb * C + c4 * 4 + u) * 2 + 1], (double)rb[tid][4 + u]);
        }
    }
}

__global__ void finalize_stats(const double* __restrict__ stats,
                               float2* __restrict__ mstat, int n, int E)
{
    int i = threadIdx.x;
    if (i >= n) return;
    double invE = 1.0 / (double)E;
    double m = stats[2 * i] * invE;
    double var = stats[2 * i + 1] * invE - m * m;
    mstat[i] = make_float2((float)m, rsqrtf((float)var + 1e-5f));
}

// Final: reads (B,E,8), writes d_out (B,8,E) with norm+relu, smem transpose.
__global__ __launch_bounds__(256) void inorm_apply_final(
    const float* __restrict__ x, int E, const float2* __restrict__ mstat,
    float* __restrict__ out)
{
    __shared__ float sm[256];
    int tid = threadIdx.x;
    int bb = blockIdx.y;
    int e0 = blockIdx.x * 32;
    float2 mr = mstat[bb * 8 + (tid & 7)];
    float v = (x[((size_t)bb * E + e0) * 8 + tid] - mr.x) * mr.y;
    sm[tid] = v > 0.f ? v : 0.f;
    __syncthreads();
    int c = tid >> 5, el = tid & 31;
    out[((size_t)bb * 8 + c) * E + e0 + el] = sm[el * 8 + c];
}

// ---------------------------------------------------------------------------
// Host driver
// ---------------------------------------------------------------------------
extern "C" void kernel_launch(void* const* d_in, const int* in_sizes, int n_in,
                              void* d_out, int out_size)
{
    (void)in_sizes; (void)n_in; (void)out_size;
    const int E0 = 16384, E1 = 32768, E2 = 65536, E3 = 131072;

    const float* fe    = (const float*)d_in[0];
    const float* skip0 = (const float*)d_in[1];
    const float* skip1 = (const float*)d_in[2];
    const float* skip2 = (const float*)d_in[3];
    const int4*  gm0   = (const int4*)d_in[4];
    const int4*  gm1   = (const int4*)d_in[5];
    const int4*  gm2   = (const int4*)d_in[6];
    const int4*  gm3   = (const int4*)d_in[7];
    const int*   up0   = (const int*)d_in[8];
    const int*   up1   = (const int*)d_in[9];
    const int*   up2   = (const int*)d_in[10];
    const float* Wup0 = (const float*)d_in[11]; const float* bup0 = (const float*)d_in[12];
    const float* Wc0  = (const float*)d_in[13]; const float* bc0  = (const float*)d_in[14];
    const float* Wup1 = (const float*)d_in[15]; const float* bup1 = (const float*)d_in[16];
    const float* Wc1  = (const float*)d_in[17]; const float* bc1  = (const float*)d_in[18];
    const float* Wup2 = (const float*)d_in[19]; const float* bup2 = (const float*)d_in[20];
    const float* Wc2  = (const float*)d_in[21]; const float* bc2  = (const float*)d_in[22];
    const float* Wupf = (const float*)d_in[23]; const float* bupf = (const float*)d_in[24];
    const float* Wcf  = (const float*)d_in[25]; const float* bcf  = (const float*)d_in[26];
    float* outp = (float*)d_out;

    float *bufA, *bufB, *bufU, *bufY, *wt; double* stats; float2* mstat;
    __nv_bfloat16 *wb; __half *wh;
    cudaGetSymbolAddress((void**)&bufA, g_bufA);
    cudaGetSymbolAddress((void**)&bufB, g_bufB);
    cudaGetSymbolAddress((void**)&bufU, g_bufU);
    cudaGetSymbolAddress((void**)&bufY, g_bufY);
    cudaGetSymbolAddress((void**)&wt,   g_wt);
    cudaGetSymbolAddress((void**)&wb,   g_wb);
    cudaGetSymbolAddress((void**)&wh,   g_wh);
    cudaGetSymbolAddress((void**)&stats, g_stats);
    cudaGetSymbolAddress((void**)&mstat, g_mstat);

    float* Wt_upf = wt + 322560;
    float* Wt_cf  = wt + 323840;

    __nv_bfloat16* Wb_up1 = wb + 589824;
    __nv_bfloat16* Wb_c1  = wb + 688128;
    __nv_bfloat16* Wb_up2 = wb + 737280;
    __nv_bfloat16* Wb_c2  = wb + 761856;
    __half* Wh_up0 = wh;
    __half* Wh_c0  = wh + 196608;

    double* stats0 = stats;
    double* stats1 = stats + 512;
    double* stats2 = stats + 768;
    double* statsF = stats + 896;
    float2* mst0 = mstat;
    float2* mst1 = mstat + 256;
    float2* mst2 = mstat + 384;
    float2* mstF = mstat + 448;

    const int SMH  = 4 * 14336 + 2 * 128 * 96 + 2048;     //  83968 (fp16 conv)
    const int SM64 = 4 * 14336 + 2 * 64 * 192 + 2048;     //  83968
    const int SM32 = 4 * 14336 + 2 * 32 * 192 + 2048;     //  71680
    cudaFuncSetAttribute(conv_t2<256>, cudaFuncAttributeMaxDynamicSharedMemorySize, SMH);
    cudaFuncSetAttribute(conv_t2<128>, cudaFuncAttributeMaxDynamicSharedMemorySize, SMH);
    cudaFuncSetAttribute(conv_t<128, 64, true>,  cudaFuncAttributeMaxDynamicSharedMemorySize, SM64);
    cudaFuncSetAttribute(conv_t<64, 64, false>,  cudaFuncAttributeMaxDynamicSharedMemorySize, SM64);
    cudaFuncSetAttribute(conv_t<64, 32, true>,   cudaFuncAttributeMaxDynamicSharedMemorySize, SM32);
    cudaFuncSetAttribute(conv_t<32, 32, false>,  cudaFuncAttributeMaxDynamicSharedMemorySize, SM32);

    // launches: wtrans+zero(0), wbf48(1), xpose(2), conv_t2 up0(3 = ncu target)
    wtrans_all<<<1267, 256>>>(Wup0, Wc0, Wup1, Wc1, Wup2, Wc2, Wupf, Wcf, wt, stats);
    wbf48<<<4176, 256>>>(Wup0, Wc0, Wup1, Wc1, Wup2, Wc2, wb, wh);
    xpose<<<dim3(E0 / 32, 256 / 32, 2), dim3(32, 8)>>>(fe, bufA, E0, 256);

    // ---- Level 0 ---- (fp16 2-term convs)
    conv_t2<256><<<dim3(E0 / 128, 2), 256, SMH>>>(bufA, gm0, Wh_up0, bup0, bufU, E0);
    unpool_skip<128><<<dim3(E1 / 32, 2), 256>>>(bufU, up0, skip0, bufY, E1, E0);
    conv_t2<128><<<dim3(E1 / 128, 2), 256, SMH>>>(bufY, gm1, Wh_c0, bc0, bufB, E1);
    inorm_partial<128, 256><<<dim3(E1 / 256, 1, 2), 256>>>(bufB, E1, stats0);
    finalize_stats<<<1, 256>>>(stats0, mst0, 256, E1);

    // ---- Level 1 ---- (up1 consumes bufB with fused norm+relu)
    conv_t<128, 64, true><<<dim3(E1 / 128, 2), 256, SM64>>>(bufB, gm1, Wb_up1, mst0, bup1, bufU, E1);
    unpool_skip<64><<<dim3(E2 / 32, 2), 256>>>(bufU, up1, skip1, bufY, E2, E1);
    conv_t<64, 64, false><<<dim3(E2 / 128, 2), 256, SM64>>>(bufY, gm2, Wb_c1, nullptr, bc1, bufA, E2);
    inorm_partial<64, 512><<<dim3(E2 / 512, 1, 2), 256>>>(bufA, E2, stats1);
    finalize_stats<<<1, 128>>>(stats1, mst1, 128, E2);

    // ---- Level 2 ---- (up2 consumes bufA with fused norm+relu)
    conv_t<64, 32, true><<<dim3(E2 / 128, 2), 256, SM32>>>(bufA, gm2, Wb_up2, mst1, bup2, bufU, E2);
    unpool_skip<32><<<dim3(E3 / 32, 2), 256>>>(bufU, up2, skip2, bufY, E3, E2);
    conv_t<32, 32, false><<<dim3(E3 / 128, 2), 256, SM32>>>(bufY, gm3, Wb_c2, nullptr, bc2, bufB, E3);
    inorm_partial<32, 1024><<<dim3(E3 / 1024, 1, 2), 256>>>(bufB, E3, stats2);
    finalize_stats<<<1, 64>>>(stats2, mst2, 64, E3);

    // ---- Final ---- (upf consumes bufB with fused norm+relu)
    conv_small<32, true><<<dim3(E3 / 256, 2), 256>>>(bufB, gm3, Wt_upf, mst2, bupf, bufU, E3);
    conv_small<8, false><<<dim3(E3 / 256, 2), 256>>>(bufU, gm3, Wt_cf, nullptr, bcf, bufY, E3);
    inorm_partial<8, 4096><<<dim3(E3 / 4096, 1, 2), 256>>>(bufY, E3, statsF);
    finalize_stats<<<1, 16>>>(statsF, mstF, 16, E3);
    inorm_apply_final<<<dim3(E3 / 32, 2), 256>>>(bufY, E3, mstF, outp);
}

// round 17
// speedup vs baseline: 1.6472x; 1.0546x over previous
#include <cuda_runtime.h>
#include <cuda_fp16.h>
#include <math.h>
#include <stdint.h>

// ---------------------------------------------------------------------------
// Static device scratch. Activations in (B, E, C) layout: x[(b*E+e)*C + c].
// ---------------------------------------------------------------------------
__device__ float  g_bufA[8388608];
__device__ float  g_bufB[8388608];
__device__ float  g_bufU[4194304];
__device__ float  g_bufY[8388608];
__device__ float  g_wt[400000];      // transposed fp32 weights (conv_small)
__device__ __align__(16) __half g_wh[387072];   // fp16 hi-only frags (6 convs)
__device__ double g_stats[1024];
__device__ float2 g_mstat[512];

__device__ __forceinline__ uint32_t smem_u32(const void* p) {
    uint32_t a;
    asm("{ .reg .u64 t; cvta.to.shared.u64 t, %1; cvt.u32.u64 %0, t; }" : "=r"(a) : "l"(p));
    return a;
}

#define STS32(a, v) \
    asm volatile("st.shared.b32 [%0], %1;" :: "r"(a), "r"(v) : "memory")

#define LDMX4(r, addr) \
    asm volatile("ldmatrix.sync.aligned.m8n8.x4.shared.b16 {%0,%1,%2,%3}, [%4];" \
        : "=r"((r)[0]), "=r"((r)[1]), "=r"((r)[2]), "=r"((r)[3]) : "r"(addr))

#define LDS64(r0, r1, addr) \
    asm volatile("ld.shared.v2.b32 {%0,%1}, [%2];" \
        : "=r"(r0), "=r"(r1) : "r"(addr))

#define CPASYNC16(saddr, gptr) \
    asm volatile("cp.async.cg.shared.global [%0], [%1], 16;" \
        :: "r"(saddr), "l"(gptr) : "memory")

#define CPCOMMIT() asm volatile("cp.async.commit_group;" ::: "memory")
#define CPWAIT0()  asm volatile("cp.async.wait_group 0;" ::: "memory")

#define MMA16816H(d, a, b0, b1) \
    asm volatile("mma.sync.aligned.m16n8k16.row.col.f32.f16.f16.f32 " \
        "{%0,%1,%2,%3}, {%4,%5,%6,%7}, {%8,%9}, {%0,%1,%2,%3};" \
        : "+f"((d)[0]), "+f"((d)[1]), "+f"((d)[2]), "+f"((d)[3]) \
        : "r"((a)[0]), "r"((a)[1]), "r"((a)[2]), "r"((a)[3]), "r"(b0), "r"(b1))

__device__ __forceinline__ uint32_t h2u(__half2 h) {
    return *reinterpret_cast<uint32_t*>(&h);
}

// ---------------------------------------------------------------------------
// fp32 weight transpose (conv_small path) + stats zeroing (fused)
// ---------------------------------------------------------------------------
__global__ void wtrans_all(const float* __restrict__ W0, const float* __restrict__ W1,
                           const float* __restrict__ W2, const float* __restrict__ W3,
                           const float* __restrict__ W4, const float* __restrict__ W5,
                           const float* __restrict__ W6, const float* __restrict__ W7,
                           float* __restrict__ wt, double* __restrict__ stats)
{
    int i = blockIdx.x * 256 + threadIdx.x;
    if (i < 1024) stats[i] = 0.0;
    if (i >= 324160) return;
    const int Ks[8]   = {1280, 640, 640, 320, 320, 160, 160, 40};
    const int Cs[8]   = {128, 128, 64, 64, 32, 32, 8, 8};
    const int offs[9] = {0, 163840, 245760, 286720, 307200, 317440, 322560, 323840, 324160};
    const float* Ws[8] = {W0, W1, W2, W3, W4, W5, W6, W7};
    int seg = 0;
    while (i >= offs[seg + 1]) seg++;
    int j = i - offs[seg];
    int K = Ks[seg], C = Cs[seg];
    int k = j / C, o = j % C;
    wt[i] = Ws[seg][(size_t)o * K + k];
}

// ---------------------------------------------------------------------------
// fp16 hi-only fragment weights for all 6 tensor convs, 48-k chunks,
// packed-6 layout (kk = cc*6 + s, s=5 pad). uint2 per lane {reg0, reg1};
// element j = (((chunk*(COUT/8)+naG)*3+ka)*32+lane)*4 + reg*2 + half;
// kk = ka*16 + (lane%4)*2 + half + reg*8.
// ---------------------------------------------------------------------------
__global__ void whf48(const float* __restrict__ W0, const float* __restrict__ W1,
                      const float* __restrict__ W2, const float* __restrict__ W3,
                      const float* __restrict__ W4, const float* __restrict__ W5,
                      __half* __restrict__ wh)
{
    int i = blockIdx.x * 256 + threadIdx.x;
    if (i >= 387072) return;
    const int CINs[6]  = {256, 128, 128, 64, 64, 32};
    const int COUTs[6] = {128, 128, 64, 64, 32, 32};
    const int offs[7]  = {0, 196608, 294912, 344064, 368640, 380928, 387072};
    const float* Ws[6] = {W0, W1, W2, W3, W4, W5};
    int seg = 0;
    while (i >= offs[seg + 1]) seg++;
    int j = i - offs[seg];
    int CIN = CINs[seg], COUT = COUTs[seg];
    int half = j & 1;
    int reg  = (j >> 1) & 1;
    int lane = (j >> 2) & 31;
    int t    = j >> 7;
    int ka   = t % 3;  t /= 3;
    int naG  = t % (COUT / 8);
    int chunk = t / (COUT / 8);
    int n  = naG * 8 + (lane >> 2);
    int kk = ka * 16 + (lane & 3) * 2 + half + reg * 8;
    int cc = kk / 6, s = kk % 6;
    float v = 0.f;
    if (s < 5) v = Ws[seg][(size_t)n * (CIN * 5) + (chunk * 8 + cc) * 5 + s];
    wh[i] = __float2half_rn(v);
}

// ---------------------------------------------------------------------------
// fe (B, C, E) -> (B, E, C) tiled transpose
// ---------------------------------------------------------------------------
__global__ void xpose(const float* __restrict__ in, float* __restrict__ outT,
                      int E, int C) {
    __shared__ float tile[32][33];
    int bb = blockIdx.z;
    int e0 = blockIdx.x * 32, c0 = blockIdx.y * 32;
    int tx = threadIdx.x, ty = threadIdx.y;          // (32, 8)
    const float* inb = in + (size_t)bb * C * E;
    float* ob = outT + (size_t)bb * E * C;
#pragma unroll
    for (int j = 0; j < 32; j += 8)
        tile[ty + j][tx] = inb[(size_t)(c0 + ty + j) * E + e0 + tx];
    __syncthreads();
#pragma unroll
    for (int j = 0; j < 32; j += 8)
        ob[(size_t)(e0 + ty + j) * C + c0 + tx] = tile[tx][ty + j];
}

// ---------------------------------------------------------------------------
// fp16 2-term tensor-core mesh conv: A split hi/lo fp16 (packed-6 layout),
// B hi-only fp16. acc = AhBh + AlBh (rel err ~2^-11 per conv).
// A tiles double-buffered + register-prefetched gathers; B double-buffered
// via cp.async staged after the barrier (race-free R12 protocol).
// NORM: fused inorm+relu on the gathered input.
// ---------------------------------------------------------------------------
template<int CIN, int COUT, bool NORM>
__global__ __launch_bounds__(256, 2) void conv_t2(
    const float* __restrict__ x, const int4* __restrict__ gemm,
    const __half* __restrict__ Wh, const float2* __restrict__ mstat,
    const float* __restrict__ bias, float* __restrict__ out, int E)
{
    constexpr int CHUNKS = CIN / 8;
    constexpr int NA = COUT / 16;
    constexpr int PITCH = 112;
    constexpr int ABUF = 128 * PITCH;
    constexpr int BU4  = COUT * 6;      // uint4 per B chunk
    constexpr int BBUF = BU4 * 16;

    extern __shared__ char smem_raw[];
    const uint32_t sAU = smem_u32(smem_raw);
    const uint32_t sBU = sAU + 4 * ABUF;
    int4* sIdx = reinterpret_cast<int4*>(smem_raw + 4 * ABUF + 2 * BBUF);

    const int tid = threadIdx.x;
    const int wid = tid >> 5, lane = tid & 31;
    const int wm = wid & 3, wn = wid >> 2;
    const int bb = blockIdx.y;
    const int e0 = blockIdx.x * 128;
    const float* xb = x + (size_t)bb * E * CIN;

    for (int i = tid; i < 128; i += 256) sIdx[i] = gemm[e0 + i];

    const int cc = tid & 7;
    const int elb = tid >> 3;

    float acc[2][NA][4];
#pragma unroll
    for (int ma = 0; ma < 2; ma++)
#pragma unroll
        for (int na = 0; na < NA; na++)
#pragma unroll
            for (int u = 0; u < 4; u++) acc[ma][na][u] = 0.f;

    const uint4* wh4 = reinterpret_cast<const uint4*>(Wh);

    auto stageB = [&](int chunk) {
        const uint32_t dst = sBU + (uint32_t)(chunk & 1) * BBUF;
        const uint4* src = wh4 + (size_t)chunk * BU4;
#pragma unroll
        for (int i = tid; i < BU4; i += 256)
            CPASYNC16(dst + (uint32_t)i * 16, src + i);
        CPCOMMIT();
    };

    stageB(0);

    float g[4][5];
    auto gather = [&](int chunk) {
        const float* xc = xb + chunk * 8 + cc;
        float2 mr = make_float2(0.f, 1.f);
        if constexpr (NORM) mr = mstat[bb * CIN + chunk * 8 + cc];
#pragma unroll
        for (int q = 0; q < 4; q++) {
            int el = elb + 32 * q;
            int4 n = sIdx[el];
            float xe = xc[(size_t)(e0 + el) * CIN];
            float f1 = xc[(size_t)n.x * CIN];
            float f2 = xc[(size_t)n.y * CIN];
            float f3 = xc[(size_t)n.z * CIN];
            float f4 = xc[(size_t)n.w * CIN];
            if constexpr (NORM) {
                xe = fmaxf((xe - mr.x) * mr.y, 0.f);
                f1 = fmaxf((f1 - mr.x) * mr.y, 0.f);
                f2 = fmaxf((f2 - mr.x) * mr.y, 0.f);
                f3 = fmaxf((f3 - mr.x) * mr.y, 0.f);
                f4 = fmaxf((f4 - mr.x) * mr.y, 0.f);
            }
            g[q][0] = xe;
            g[q][1] = f1 + f3;  g[q][2] = f2 + f4;
            g[q][3] = fabsf(f1 - f3);  g[q][4] = fabsf(f2 - f4);
        }
    };

    __syncthreads();   // sIdx ready
    gather(0);

    for (int chunk = 0; chunk < CHUNKS; chunk++) {
        const uint32_t bufHi = sAU + (uint32_t)((chunk & 1) * 2) * ABUF;
        const uint32_t bufLo = bufHi + ABUF;
#pragma unroll
        for (int q = 0; q < 4; q++) {
            int el = elb + 32 * q;
            uint32_t base = (uint32_t)el * PITCH + (uint32_t)cc * 12;
            __half h0 = __float2half_rn(g[q][0]);
            __half h1 = __float2half_rn(g[q][1]);
            __half h2 = __float2half_rn(g[q][2]);
            __half h3 = __float2half_rn(g[q][3]);
            __half h4 = __float2half_rn(g[q][4]);
            __half z  = __float2half_rn(0.f);
            __half r0 = __float2half_rn(g[q][0] - __half2float(h0));
            __half r1 = __float2half_rn(g[q][1] - __half2float(h1));
            __half r2 = __float2half_rn(g[q][2] - __half2float(h2));
            __half r3 = __float2half_rn(g[q][3] - __half2float(h3));
            __half r4 = __float2half_rn(g[q][4] - __half2float(h4));
            STS32(bufHi + base,     h2u(__halves2half2(h0, h1)));
            STS32(bufHi + base + 4, h2u(__halves2half2(h2, h3)));
            STS32(bufHi + base + 8, h2u(__halves2half2(h4, z)));
            STS32(bufLo + base,     h2u(__halves2half2(r0, r1)));
            STS32(bufLo + base + 4, h2u(__halves2half2(r2, r3)));
            STS32(bufLo + base + 8, h2u(__halves2half2(r4, z)));
        }
        CPWAIT0();
        __syncthreads();   // A stores + B visible; mma(chunk-1) done
        if (chunk + 1 < CHUNKS) stageB(chunk + 1);
        if (chunk + 1 < CHUNKS) gather(chunk + 1);
        const uint32_t bB = sBU + (uint32_t)(chunk & 1) * BBUF;
#pragma unroll
        for (int ka = 0; ka < 3; ka++) {
            uint32_t ah[2][4], al[2][4];
#pragma unroll
            for (int ma = 0; ma < 2; ma++) {
                uint32_t off = (uint32_t)(wm * 32 + ma * 16 + (lane & 15)) * PITCH
                             + (uint32_t)ka * 32 + ((lane >> 4) * 16);
                LDMX4(ah[ma], bufHi + off);
                LDMX4(al[ma], bufLo + off);
            }
#pragma unroll
            for (int na = 0; na < NA; na++) {
                uint32_t wx, wy;
                LDS64(wx, wy,
                      bB + (uint32_t)(((wn * NA + na) * 3 + ka) * 32 + lane) * 8);
#pragma unroll
                for (int ma = 0; ma < 2; ma++) {
                    MMA16816H(acc[ma][na], ah[ma], wx, wy);
                    MMA16816H(acc[ma][na], al[ma], wx, wy);
                }
            }
        }
    }

    // ---- epilogue: acc + bias -> out ----
    const int rbase = e0 + wm * 32 + (lane >> 2);
#pragma unroll
    for (int ma = 0; ma < 2; ma++) {
#pragma unroll
        for (int na = 0; na < NA; na++) {
            int col = wn * NA * 8 + na * 8 + (lane & 3) * 2;
            float bx = bias[col], by = bias[col + 1];
            int row0 = rbase + ma * 16;
            float* p0 = out + ((size_t)bb * E + row0) * COUT + col;
            float* p1 = p0 + (size_t)8 * COUT;
            *reinterpret_cast<float2*>(p0) =
                make_float2(acc[ma][na][0] + bx, acc[ma][na][1] + by);
            *reinterpret_cast<float2*>(p1) =
                make_float2(acc[ma][na][2] + bx, acc[ma][na][3] + by);
        }
    }
}

// ---------------------------------------------------------------------------
// Small-Cout mesh-conv (COUT = 8), fp32, optional fused inorm+relu on input
// ---------------------------------------------------------------------------
template<int CIN, bool NORM>
__global__ __launch_bounds__(256) void conv_small(
    const float* __restrict__ x, const int4* __restrict__ gemm,
    const float* __restrict__ Wt, const float2* __restrict__ mstat,
    const float* __restrict__ bias, float* __restrict__ out, int E)
{
    constexpr int K = CIN * 5;
    __shared__ float sW[K * 8];
    __shared__ float2 sM[CIN];
    int tid = threadIdx.x;
    int bb = blockIdx.y;
    for (int i = tid; i < K * 8; i += 256) sW[i] = Wt[i];
    if (NORM && tid < CIN) sM[tid] = mstat[bb * CIN + tid];
    float acc[8];
#pragma unroll
    for (int o = 0; o < 8; o++) acc[o] = bias[o];
    __syncthreads();

    int e = blockIdx.x * 256 + tid;
    int4 n = gemm[e];
    const float* xb = x + (size_t)bb * E * CIN;
    const float4* r0 = reinterpret_cast<const float4*>(xb + (size_t)e * CIN);
    const float4* r1 = reinterpret_cast<const float4*>(xb + (size_t)n.x * CIN);
    const float4* r2 = reinterpret_cast<const float4*>(xb + (size_t)n.y * CIN);
    const float4* r3 = reinterpret_cast<const float4*>(xb + (size_t)n.z * CIN);
    const float4* r4 = reinterpret_cast<const float4*>(xb + (size_t)n.w * CIN);

#pragma unroll 2
    for (int c4 = 0; c4 < CIN / 4; c4++) {
        float4 xe = r0[c4], a1 = r1[c4], a2 = r2[c4], a3 = r3[c4], a4 = r4[c4];
#define PROC(COMP, CC)                                                         \
        {                                                                      \
            float xv = xe.COMP, v1 = a1.COMP, v2 = a2.COMP,                    \
                  v3 = a3.COMP, v4 = a4.COMP;                                  \
            if constexpr (NORM) {                                              \
                float2 mm = sM[c4 * 4 + CC];                                   \
                xv = fmaxf((xv - mm.x) * mm.y, 0.f);                           \
                v1 = fmaxf((v1 - mm.x) * mm.y, 0.f);                           \
                v2 = fmaxf((v2 - mm.x) * mm.y, 0.f);                           \
                v3 = fmaxf((v3 - mm.x) * mm.y, 0.f);                           \
                v4 = fmaxf((v4 - mm.x) * mm.y, 0.f);                           \
            }                                                                  \
            float g0 = xv;                                                     \
            float s1 = v1 + v3;                                                \
            float s2 = v2 + v4;                                                \
            float d1 = fabsf(v1 - v3);                                         \
            float d2 = fabsf(v2 - v4);                                         \
            const float* w = &sW[(c4 * 4 + CC) * 5 * 8];                       \
            for (int o = 0; o < 8; o++)                                        \
                acc[o] += g0 * w[o] + s1 * w[8 + o] + s2 * w[16 + o]           \
                        + d1 * w[24 + o] + d2 * w[32 + o];                     \
        }
        PROC(x, 0) PROC(y, 1) PROC(z, 2) PROC(w, 3)
#undef PROC
    }
    float* po = out + ((size_t)bb * E + e) * 8;
    *reinterpret_cast<float4*>(po)     = make_float4(acc[0], acc[1], acc[2], acc[3]);
    *reinterpret_cast<float4*>(po + 4) = make_float4(acc[4], acc[5], acc[6], acc[7]);
}

// ---------------------------------------------------------------------------
// unpool + skip
// ---------------------------------------------------------------------------
template<int C>
__global__ __launch_bounds__(256) void unpool_skip(
    const float* __restrict__ up, const int* __restrict__ unpool,
    const float* __restrict__ skip, float* __restrict__ out,
    int Eout, int Ein)
{
    constexpr int TE = 32;
    __shared__ float ssk[C][TE + 1];
    __shared__ int su[TE];
    int tid = threadIdx.x;
    int bb = blockIdx.y;
    int e0 = blockIdx.x * TE;
    if (tid < TE) su[tid] = unpool[e0 + tid];
    const float* skb = skip + (size_t)bb * C * Eout;
    for (int i = tid; i < C * TE; i += 256) {
        int c = i >> 5, e = i & 31;
        ssk[c][e] = skb[(size_t)c * Eout + e0 + e];
    }
    __syncthreads();
    const float* upb = up + (size_t)bb * Ein * C;
    float* ob = out + ((size_t)bb * Eout + e0) * C;
    for (int i = tid; i < C * TE; i += 256) {
        int el = i / C, c = i % C;
        ob[(size_t)el * C + c] = upb[(size_t)su[el] * C + c] + ssk[c][el];
    }
}

// ---------------------------------------------------------------------------
// Instance norm: partial stats + finalize
// ---------------------------------------------------------------------------
template<int C, int CHUNK>
__global__ __launch_bounds__(256) void inorm_partial(
    const float* __restrict__ x, int E, double* __restrict__ stats)
{
    constexpr int C4 = C / 4;
    constexpr int ESTEP = 256 / C4;
    __shared__ float rb[256][8];
    int tid = threadIdx.x;
    int c4 = tid % C4, er = tid / C4;
    int bb = blockIdx.z;
    int e0 = blockIdx.x * CHUNK;
    const float4* xb4 = reinterpret_cast<const float4*>(x + ((size_t)bb * E + e0) * C) + c4;
    float s0 = 0, s1 = 0, s2 = 0, s3 = 0, q0 = 0, q1 = 0, q2 = 0, q3 = 0;
    for (int e = er; e < CHUNK; e += ESTEP) {
        float4 v = xb4[(size_t)e * C4];
        s0 += v.x; q0 += v.x * v.x;
        s1 += v.y; q1 += v.y * v.y;
        s2 += v.z; q2 += v.z * v.z;
        s3 += v.w; q3 += v.w * v.w;
    }
    rb[tid][0] = s0; rb[tid][1] = s1; rb[tid][2] = s2; rb[tid][3] = s3;
    rb[tid][4] = q0; rb[tid][5] = q1; rb[tid][6] = q2; rb[tid][7] = q3;
    __syncthreads();
    for (int st = ESTEP / 2; st >= 1; st >>= 1) {
        if (er < st) {
#pragma unroll
            for (int u = 0; u < 8; u++) rb[tid][u] += rb[tid + st * C4][u];
        }
        __syncthreads();
    }
    if (er == 0) {
#pragma unroll
        for (int u = 0; u < 4; u++) {
            atomicAdd(&stats[((size_t)bb * C + c4 * 4 + u) * 2],     (double)rb[tid][u]);
            atomicAdd(&stats[((size_t)bb * C + c4 * 4 + u) * 2 + 1], (double)rb[tid][4 + u]);
        }
    }
}

__global__ void finalize_stats(const double* __restrict__ stats,
                               float2* __restrict__ mstat, int n, int E)
{
    int i = threadIdx.x;
    if (i >= n) return;
    double invE = 1.0 / (double)E;
    double m = stats[2 * i] * invE;
    double var = stats[2 * i + 1] * invE - m * m;
    mstat[i] = make_float2((float)m, rsqrtf((float)var + 1e-5f));
}

// Final: reads (B,E,8), writes d_out (B,8,E) with norm+relu, smem transpose.
__global__ __launch_bounds__(256) void inorm_apply_final(
    const float* __restrict__ x, int E, const float2* __restrict__ mstat,
    float* __restrict__ out)
{
    __shared__ float sm[256];
    int tid = threadIdx.x;
    int bb = blockIdx.y;
    int e0 = blockIdx.x * 32;
    float2 mr = mstat[bb * 8 + (tid & 7)];
    float v = (x[((size_t)bb * E + e0) * 8 + tid] - mr.x) * mr.y;
    sm[tid] = v > 0.f ? v : 0.f;
    __syncthreads();
    int c = tid >> 5, el = tid & 31;
    out[((size_t)bb * 8 + c) * E + e0 + el] = sm[el * 8 + c];
}

// ---------------------------------------------------------------------------
// Host driver
// ---------------------------------------------------------------------------
extern "C" void kernel_launch(void* const* d_in, const int* in_sizes, int n_in,
                              void* d_out, int out_size)
{
    (void)in_sizes; (void)n_in; (void)out_size;
    const int E0 = 16384, E1 = 32768, E2 = 65536, E3 = 131072;

    const float* fe    = (const float*)d_in[0];
    const float* skip0 = (const float*)d_in[1];
    const float* skip1 = (const float*)d_in[2];
    const float* skip2 = (const float*)d_in[3];
    const int4*  gm0   = (const int4*)d_in[4];
    const int4*  gm1   = (const int4*)d_in[5];
    const int4*  gm2   = (const int4*)d_in[6];
    const int4*  gm3   = (const int4*)d_in[7];
    const int*   up0   = (const int*)d_in[8];
    const int*   up1   = (const int*)d_in[9];
    const int*   up2   = (const int*)d_in[10];
    const float* Wup0 = (const float*)d_in[11]; const float* bup0 = (const float*)d_in[12];
    const float* Wc0  = (const float*)d_in[13]; const float* bc0  = (const float*)d_in[14];
    const float* Wup1 = (const float*)d_in[15]; const float* bup1 = (const float*)d_in[16];
    const float* Wc1  = (const float*)d_in[17]; const float* bc1  = (const float*)d_in[18];
    const float* Wup2 = (const float*)d_in[19]; const float* bup2 = (const float*)d_in[20];
    const float* Wc2  = (const float*)d_in[21]; const float* bc2  = (const float*)d_in[22];
    const float* Wupf = (const float*)d_in[23]; const float* bupf = (const float*)d_in[24];
    const float* Wcf  = (const float*)d_in[25]; const float* bcf  = (const float*)d_in[26];
    float* outp = (float*)d_out;

    float *bufA, *bufB, *bufU, *bufY, *wt; double* stats; float2* mstat;
    __half *wh;
    cudaGetSymbolAddress((void**)&bufA, g_bufA);
    cudaGetSymbolAddress((void**)&bufB, g_bufB);
    cudaGetSymbolAddress((void**)&bufU, g_bufU);
    cudaGetSymbolAddress((void**)&bufY, g_bufY);
    cudaGetSymbolAddress((void**)&wt,   g_wt);
    cudaGetSymbolAddress((void**)&wh,   g_wh);
    cudaGetSymbolAddress((void**)&stats, g_stats);
    cudaGetSymbolAddress((void**)&mstat, g_mstat);

    float* Wt_upf = wt + 322560;
    float* Wt_cf  = wt + 323840;

    __half* Wh_up0 = wh;
    __half* Wh_c0  = wh + 196608;
    __half* Wh_up1 = wh + 294912;
    __half* Wh_c1  = wh + 344064;
    __half* Wh_up2 = wh + 368640;
    __half* Wh_c2  = wh + 380928;

    double* stats0 = stats;
    double* stats1 = stats + 512;
    double* stats2 = stats + 768;
    double* statsF = stats + 896;
    float2* mst0 = mstat;
    float2* mst1 = mstat + 256;
    float2* mst2 = mstat + 384;
    float2* mstF = mstat + 448;

    const int SM128 = 4 * 14336 + 2 * 128 * 96 + 2048;   // 83968
    const int SM64  = 4 * 14336 + 2 * 64 * 96 + 2048;    // 71680
    const int SM32  = 4 * 14336 + 2 * 32 * 96 + 2048;    // 65536
    cudaFuncSetAttribute(conv_t2<256, 128, false>, cudaFuncAttributeMaxDynamicSharedMemorySize, SM128);
    cudaFuncSetAttribute(conv_t2<128, 128, false>, cudaFuncAttributeMaxDynamicSharedMemorySize, SM128);
    cudaFuncSetAttribute(conv_t2<128, 64, true>,   cudaFuncAttributeMaxDynamicSharedMemorySize, SM64);
    cudaFuncSetAttribute(conv_t2<64, 64, false>,   cudaFuncAttributeMaxDynamicSharedMemorySize, SM64);
    cudaFuncSetAttribute(conv_t2<64, 32, true>,    cudaFuncAttributeMaxDynamicSharedMemorySize, SM32);
    cudaFuncSetAttribute(conv_t2<32, 32, false>,   cudaFuncAttributeMaxDynamicSharedMemorySize, SM32);

    // launches: wtrans+zero(0), whf48(1), xpose(2), conv_t2 up0(3 = ncu target)
    wtrans_all<<<1267, 256>>>(Wup0, Wc0, Wup1, Wc1, Wup2, Wc2, Wupf, Wcf, wt, stats);
    whf48<<<1512, 256>>>(Wup0, Wc0, Wup1, Wc1, Wup2, Wc2, wh);
    xpose<<<dim3(E0 / 32, 256 / 32, 2), dim3(32, 8)>>>(fe, bufA, E0, 256);

    // ---- Level 0 ----
    conv_t2<256, 128, false><<<dim3(E0 / 128, 2), 256, SM128>>>(bufA, gm0, Wh_up0, nullptr, bup0, bufU, E0);
    unpool_skip<128><<<dim3(E1 / 32, 2), 256>>>(bufU, up0, skip0, bufY, E1, E0);
    conv_t2<128, 128, false><<<dim3(E1 / 128, 2), 256, SM128>>>(bufY, gm1, Wh_c0, nullptr, bc0, bufB, E1);
    inorm_partial<128, 256><<<dim3(E1 / 256, 1, 2), 256>>>(bufB, E1, stats0);
    finalize_stats<<<1, 256>>>(stats0, mst0, 256, E1);

    // ---- Level 1 ---- (up1 consumes bufB with fused norm+relu)
    conv_t2<128, 64, true><<<dim3(E1 / 128, 2), 256, SM64>>>(bufB, gm1, Wh_up1, mst0, bup1, bufU, E1);
    unpool_skip<64><<<dim3(E2 / 32, 2), 256>>>(bufU, up1, skip1, bufY, E2, E1);
    conv_t2<64, 64, false><<<dim3(E2 / 128, 2), 256, SM64>>>(bufY, gm2, Wh_c1, nullptr, bc1, bufA, E2);
    inorm_partial<64, 512><<<dim3(E2 / 512, 1, 2), 256>>>(bufA, E2, stats1);
    finalize_stats<<<1, 128>>>(stats1, mst1, 128, E2);

    // ---- Level 2 ---- (up2 consumes bufA with fused norm+relu)
    conv_t2<64, 32, true><<<dim3(E2 / 128, 2), 256, SM32>>>(bufA, gm2, Wh_up2, mst1, bup2, bufU, E2);
    unpool_skip<32><<<dim3(E3 / 32, 2), 256>>>(bufU, up2, skip2, bufY, E3, E2);
    conv_t2<32, 32, false><<<dim3(E3 / 128, 2), 256, SM32>>>(bufY, gm3, Wh_c2, nullptr, bc2, bufB, E3);
    inorm_partial<32, 1024><<<dim3(E3 / 1024, 1, 2), 256>>>(bufB, E3, stats2);
    finalize_stats<<<1, 64>>>(stats2, mst2, 64, E3);

    // ---- Final ---- (upf consumes bufB with fused norm+relu)
    conv_small<32, true><<<dim3(E3 / 256, 2), 256>>>(bufB, gm3, Wt_upf, mst2, bupf, bufU, E3);
    conv_small<8, false><<<dim3(E3 / 256, 2), 256>>>(bufU, gm3, Wt_cf, nullptr, bcf, bufY, E3);
    inorm_partial<8, 4096><<<dim3(E3 / 4096, 1, 2), 256>>>(bufY, E3, statsF);
    finalize_stats<<<1, 16>>>(statsF, mstF, 16, E3);
    inorm_apply_final<<<dim3(E3 / 32, 2), 256>>>(bufY, E3, mstF, outp);
}